// round 12
// baseline (speedup 1.0000x reference)
#include <cuda_runtime.h>
#include <cuda_fp16.h>
#include <cstdint>

#define B_   32
#define SV   512
#define SQ   256
#define SC   512
#define D_   1024
#define H_   8
#define DHD  128
#define N3   3072
#define GK   1024

// ---------------- scratch (device globals; no allocations allowed) ----------------
__device__ float g_gate_v4q[32768];
__device__ float g_gate_q4v[32768];
__device__ float g_mean_v[32768];
__device__ float g_mean_q[32768];

// fp16 activations + transposed weights for GEMMs
__device__ __half g_a_v[16777216];
__device__ __half g_a_q[8388608];
__device__ __half g_a_c[16777216];
__device__ __half g_wt[12582912];
// offsets: Wv=0, Wq=3145728, Wc=6291456, Wvo=9437184, Wqo=10485760, Wco=11534336

// fp16 K/Q/V in [B,H,T,dh] layout (UNGATED; mask pre-applied; mem token at t=0)
__device__ __half g_vK[16809984], g_vQ[16777216], g_vV[16809984];
__device__ __half g_qK[8388608],  g_qQ[8388608],  g_qV[8388608];
__device__ __half g_cK[16809984], g_cQ[16777216], g_cV[16809984];

// ---------------- base-target tensor helpers ----------------
__device__ __forceinline__ uint32_t smem_u32(const void* p) {
    uint32_t a;
    asm("{ .reg .u64 t; cvta.to.shared.u64 t, %1; cvt.u32.u64 %0, t; }" : "=r"(a) : "l"(p));
    return a;
}
__device__ __forceinline__ void cp16(uint32_t dst, const void* src) {
    asm volatile("cp.async.cg.shared.global [%0], [%1], 16;" :: "r"(dst), "l"(src));
}
__device__ __forceinline__ void cp16z(uint32_t dst, const void* src, int sz) {
    asm volatile("cp.async.cg.shared.global [%0], [%1], 16, %2;" :: "r"(dst), "l"(src), "r"(sz));
}
__device__ __forceinline__ void cp_commit() { asm volatile("cp.async.commit_group;" ::: "memory"); }
__device__ __forceinline__ void cp_wait1()  { asm volatile("cp.async.wait_group 1;" ::: "memory"); }
__device__ __forceinline__ void cp_wait0()  { asm volatile("cp.async.wait_group 0;" ::: "memory"); }

__device__ __forceinline__ void ldmx4(uint32_t* r, uint32_t addr) {
    asm volatile("ldmatrix.sync.aligned.m8n8.x4.shared.b16 {%0,%1,%2,%3}, [%4];"
                 : "=r"(r[0]), "=r"(r[1]), "=r"(r[2]), "=r"(r[3]) : "r"(addr));
}
__device__ __forceinline__ void ldmx4t(uint32_t* r, uint32_t addr) {
    asm volatile("ldmatrix.sync.aligned.m8n8.x4.trans.shared.b16 {%0,%1,%2,%3}, [%4];"
                 : "=r"(r[0]), "=r"(r[1]), "=r"(r[2]), "=r"(r[3]) : "r"(addr));
}
__device__ __forceinline__ void mma16816(float* d, const uint32_t* a, uint32_t b0, uint32_t b1) {
    asm volatile("mma.sync.aligned.m16n8k16.row.col.f32.f16.f16.f32 "
                 "{%0,%1,%2,%3}, {%4,%5,%6,%7}, {%8,%9}, {%0,%1,%2,%3};"
                 : "+f"(d[0]), "+f"(d[1]), "+f"(d[2]), "+f"(d[3])
                 : "r"(a[0]), "r"(a[1]), "r"(a[2]), "r"(a[3]), "r"(b0), "r"(b1));
}

// ---------------- fp16 pack helpers ----------------
__device__ __forceinline__ uint32_t packh2(float x, float y) {
    __half2 h = __floats2half2_rn(x, y);
    return *(uint32_t*)&h;
}
__device__ __forceinline__ void store_h2(__half* H, size_t idx, float x, float y) {
    *(__half2*)(H + idx) = __floats2half2_rn(x, y);
}

// ---------------- fused conversion kernels ----------------
struct ActArgs { const float* x[3]; __half* out[3]; int nblk0, nblk1; };
__global__ void cvt_act_kernel(ActArgs a) {
    int bx = blockIdx.x;
    int z, base;
    if (bx < a.nblk0) { z = 0; base = 0; }
    else if (bx < a.nblk0 + a.nblk1) { z = 1; base = a.nblk0; }
    else { z = 2; base = a.nblk0 + a.nblk1; }
    int idx = (bx - base) * 256 + threadIdx.x;
    float4 v = ((const float4*)a.x[z])[idx];
    v.x = fmaxf(v.x, 0.f); v.y = fmaxf(v.y, 0.f);
    v.z = fmaxf(v.z, 0.f); v.w = fmaxf(v.w, 0.f);
    uint2 o;
    o.x = packh2(v.x, v.y);
    o.y = packh2(v.z, v.w);
    ((uint2*)a.out[z])[idx] = o;
}

struct WTArgs { const float* W[6]; __half* out[6]; int N[6]; };
__global__ void cvt_wT_kernel(WTArgs a) {
    int z = blockIdx.z;
    const float* W = a.W[z];
    __half* th = a.out[z];
    int N = a.N[z];
    if (blockIdx.x * 32 >= N) return;
    __shared__ float t[32][33];
    int n0 = blockIdx.x * 32, k0 = blockIdx.y * 32;
    int tx = threadIdx.x, ty = threadIdx.y;   // (32, 8)
    #pragma unroll
    for (int r = 0; r < 4; r++)
        t[ty + 8 * r][tx] = W[(size_t)(k0 + ty + 8 * r) * N + n0 + tx];
    __syncthreads();
    #pragma unroll
    for (int r = 0; r < 4; r++) {
        size_t o = (size_t)(n0 + ty + 8 * r) * GK + k0 + tx;
        th[o] = __float2half_rn(t[tx][ty + 8 * r]);
    }
}

// ---------------- small fused kernels ----------------
struct MeanArgs { const float* x[2]; const float* mask[2]; float* out[2]; int S[2]; };
__global__ void mean_relu_kernel(MeanArgs a) {
    __shared__ float red[256];
    __shared__ float sinv;
    int z = blockIdx.z;
    int S = a.S[z];
    int b = blockIdx.y;
    const float* mp = a.mask[z] + (size_t)b * S;
    float s = 0.f;
    for (int t = threadIdx.x; t < S; t += 256) s += mp[t];
    red[threadIdx.x] = s;
    __syncthreads();
    for (int w = 128; w > 0; w >>= 1) {
        if (threadIdx.x < w) red[threadIdx.x] += red[threadIdx.x + w];
        __syncthreads();
    }
    if (threadIdx.x == 0) sinv = 1.f / red[0];
    __syncthreads();
    int d = blockIdx.x * 256 + threadIdx.x;
    const float* xp = a.x[z] + (size_t)b * S * D_ + d;
    float a0 = 0.f, a1 = 0.f, a2 = 0.f, a3 = 0.f;
    for (int t = 0; t < S; t += 4) {
        a0 = fmaf(xp[(size_t)(t + 0) * D_], mp[t + 0], a0);
        a1 = fmaf(xp[(size_t)(t + 1) * D_], mp[t + 1], a1);
        a2 = fmaf(xp[(size_t)(t + 2) * D_], mp[t + 2], a2);
        a3 = fmaf(xp[(size_t)(t + 3) * D_], mp[t + 3], a3);
    }
    a.out[z][b * D_ + d] = fmaxf(((a0 + a1) + (a2 + a3)) * sinv, 0.f);
}

// gate: k-parallel (4 k-groups x 128 n), smem reduce. grid (8, B, 2), block 512.
struct GateArgs { const float* mean[2]; const float* W[2]; const float* bias[2]; float* out[2]; };
__global__ __launch_bounds__(512) void gate_kernel(GateArgs a) {
    __shared__ float sm[D_];
    __shared__ float red[512];
    int z = blockIdx.z;
    int b = blockIdx.y;
    int tid = threadIdx.x;
    int g = tid >> 7;            // k-group 0..3
    int nl = tid & 127;
    const float* rmean = a.mean[z];
    const float* W = a.W[z];
    for (int k = tid; k < D_; k += 512) sm[k] = rmean[b * D_ + k];
    __syncthreads();
    int n = blockIdx.x * 128 + nl;
    int k0 = g * 256;
    float acc = 0.f;
    #pragma unroll 8
    for (int k = 0; k < 256; k++)
        acc = fmaf(sm[k0 + k], W[(size_t)(k0 + k) * D_ + n], acc);
    red[tid] = acc;
    __syncthreads();
    if (g == 0) {
        float t = red[nl] + red[nl + 128] + red[nl + 256] + red[nl + 384] + a.bias[z][n];
        a.out[z][b * D_ + n] = 1.f + 1.f / (1.f + __expf(-t));
    }
}

// mem token at t=0 (UNGATED; gating now happens inside attention)
struct MemArgs { __half* K[2]; __half* V[2]; const float* mk[2]; const float* mv[2]; int T[2]; };
__global__ void memtok_kernel(MemArgs a) {
    int z = blockIdx.y;
    int b = blockIdx.x;
    int i = threadIdx.x;
    int h = i >> 7;
    size_t idx = ((size_t)(b * H_ + h) * a.T[z]) * DHD + (i & 127);
    a.K[z][idx] = __float2half_rn(32.f * a.mk[z][i]);
    a.V[z][idx] = __float2half_rn(a.mv[z][i]);
}

// ---------------- mma.sync fp16 GEMM (3-stream merged, 2-stage pipeline) ----------------
#define ROWB 40
#define MAT_BYTES (128 * ROWB * 2)
#define STAGE_BYTES (2 * MAT_BYTES)          // 20480
#define MMA_SMEM_BYTES (2 * STAGE_BYTES)     // 40960

struct GemmS {
    const __half *A, *B;
    const float *bias, *mask;
    __half *oK, *oQ, *oV;
    float* C;
    int S, T, hasMem;
};
struct Gemm3 { GemmS s[3]; int nby0, nby1; };

template <bool MASK, bool SPLIT>
__global__ __launch_bounds__(128, 2) void mma_gemm_kernel(Gemm3 ga, int N)
{
    extern __shared__ char smem[];
    uint32_t sbase = smem_u32(smem);
    int tid = threadIdx.x;
    int wid = tid >> 5, lane = tid & 31;
    int byg = blockIdx.y;
    int z, ybase;
    if (byg < ga.nby0) { z = 0; ybase = 0; }
    else if (byg < ga.nby0 + ga.nby1) { z = 1; ybase = ga.nby0; }
    else { z = 2; ybase = ga.nby0 + ga.nby1; }
    const GemmS s = ga.s[z];
    int bm = (byg - ybase) * 128, bn = blockIdx.x * 128;
    int wm = (wid & 1) * 64;
    int wn = (wid >> 1) * 64;

    const __half* srcs[2] = { s.A + (size_t)bm * GK, s.B + (size_t)bn * GK };

    float acc[4][8][4];
    #pragma unroll
    for (int i = 0; i < 4; i++)
        #pragma unroll
        for (int j = 0; j < 8; j++)
            #pragma unroll
            for (int k = 0; k < 4; k++) acc[i][j][k] = 0.f;

    int lrow = tid >> 2, lc = tid & 3;
    auto load_stage = [&](int kc, int st2) {
        uint32_t st = sbase + st2 * STAGE_BYTES;
        int k0 = kc * 32;
        #pragma unroll
        for (int m = 0; m < 2; m++) {
            const __half* src = srcs[m];
            uint32_t dst = st + m * MAT_BYTES;
            #pragma unroll
            for (int it = 0; it < 4; it++) {
                int row = lrow + it * 32;
                cp16(dst + row * 80 + lc * 16, src + (size_t)row * GK + k0 + lc * 8);
            }
        }
        cp_commit();
    };

    load_stage(0, 0);

    const int NK = GK / 32;
    for (int kc = 0; kc < NK; kc++) {
        if (kc + 1 < NK) { load_stage(kc + 1, (kc + 1) & 1); cp_wait1(); }
        else cp_wait0();
        __syncthreads();
        uint32_t st = sbase + (kc & 1) * STAGE_BYTES;
        uint32_t sA = st, sB = st + MAT_BYTES;
        #pragma unroll
        for (int ks = 0; ks < 32; ks += 16) {
            uint32_t ah[4][4];
            int arow = wm + (lane & 15);
            int ak = ks + ((lane >> 4) << 3);
            #pragma unroll
            for (int mt = 0; mt < 4; mt++)
                ldmx4(ah[mt], sA + (uint32_t)(((arow + mt * 16) * ROWB + ak) * 2));
            int r = lane & 7, qsel = lane >> 3;
            #pragma unroll
            for (int nt = 0; nt < 4; nt++) {
                int nn = wn + nt * 16 + ((qsel >> 1) << 3) + r;
                int kk = ks + ((qsel & 1) << 3);
                uint32_t bh[4];
                ldmx4(bh, sB + (uint32_t)((nn * ROWB + kk) * 2));
                #pragma unroll
                for (int mt = 0; mt < 4; mt++) {
                    mma16816(acc[mt][nt * 2 + 0], ah[mt], bh[0], bh[1]);
                    mma16816(acc[mt][nt * 2 + 1], ah[mt], bh[2], bh[3]);
                }
            }
        }
        __syncthreads();
    }

    if (!SPLIT) {
        #pragma unroll
        for (int mt = 0; mt < 4; mt++) {
            int r0 = bm + wm + mt * 16 + (lane >> 2);
            float m0 = MASK ? s.mask[r0] : 1.f;
            float m1 = MASK ? s.mask[r0 + 8] : 1.f;
            #pragma unroll
            for (int nt = 0; nt < 8; nt++) {
                int col = bn + wn + nt * 8 + ((lane & 3) << 1);
                float2 bb = *(const float2*)&s.bias[col];
                float2 o0, o1;
                o0.x = (acc[mt][nt][0] + bb.x) * m0; o0.y = (acc[mt][nt][1] + bb.y) * m0;
                o1.x = (acc[mt][nt][2] + bb.x) * m1; o1.y = (acc[mt][nt][3] + bb.y) * m1;
                *(float2*)(s.C + (size_t)r0 * N + col) = o0;
                *(float2*)(s.C + (size_t)(r0 + 8) * N + col) = o1;
            }
        }
    } else {
        int colbase = bn + wn;
        int part = colbase >> 10;           // 0=k, 1=q, 2=v
        int hh = (colbase & 1023) >> 7;
        int dwarp = colbase & 127;
        int b = bm / s.S;
        int s0 = bm % s.S;
        size_t bh64 = (size_t)(b * H_ + hh);
        #pragma unroll
        for (int mt = 0; mt < 4; mt++) {
            int rl0 = wm + mt * 16 + (lane >> 2);
            int gr0 = bm + rl0;
            float mk0 = MASK ? s.mask[gr0] : 1.f;
            float mk1 = MASK ? s.mask[gr0 + 8] : 1.f;
            int s_0 = s0 + rl0, s_1 = s_0 + 8;
            #pragma unroll
            for (int nt = 0; nt < 8; nt++) {
                int d = dwarp + nt * 8 + ((lane & 3) << 1);
                int col = colbase + nt * 8 + ((lane & 3) << 1);
                float2 bb = *(const float2*)&s.bias[col];
                float x0 = (acc[mt][nt][0] + bb.x) * mk0;
                float y0 = (acc[mt][nt][1] + bb.y) * mk0;
                float x1 = (acc[mt][nt][2] + bb.x) * mk1;
                float y1 = (acc[mt][nt][3] + bb.y) * mk1;
                if (part == 0) {
                    store_h2(s.oK, (bh64 * s.T + (s_0 + s.hasMem)) * DHD + d, x0, y0);
                    store_h2(s.oK, (bh64 * s.T + (s_1 + s.hasMem)) * DHD + d, x1, y1);
                } else if (part == 1) {
                    store_h2(s.oQ, (bh64 * s.S + s_0) * DHD + d, x0, y0);
                    store_h2(s.oQ, (bh64 * s.S + s_1) * DHD + d, x1, y1);
                } else {
                    store_h2(s.oV, (bh64 * s.T + (s_0 + s.hasMem)) * DHD + d, x0, y0);
                    store_h2(s.oV, (bh64 * s.T + (s_1 + s.hasMem)) * DHD + d, x1, y1);
                }
            }
        }
    }
}

// ---------------- tensor-core flash attention ----------------
// fp16, 3-stream merged, exp2 softmax, Q/K gating applied in smem.
#define APAD 136
constexpr int A_Q   = 0;
constexpr int A_ST0 = 128 * APAD * 2;
constexpr int A_STG = 2 * 64 * APAD * 2;
constexpr int A_K   = 0;
constexpr int A_V   = 64 * APAD * 2;
constexpr int A_KM  = A_ST0 + 2 * A_STG;
constexpr int A_GH  = A_KM + 2 * 64 * 4;
constexpr int ATT_SMEM_BYTES = A_GH + 64 * 4;   // + gate half2[64]

struct AttnS {
    const __half *K, *Q, *V;
    const float *mask, *resid, *gate;
    __half* outA;
    int S, T, hasMem;
};
struct Attn3 { AttnS s[3]; int nbx0, nbx1; };

__global__ __launch_bounds__(256, 2) void attn_mma_kernel(Attn3 aa)
{
    extern __shared__ char smc[];
    uint32_t sb = smem_u32(smc);
    float* km = (float*)(smc + A_KM);
    __half2* gh = (__half2*)(smc + A_GH);
    int tid = threadIdx.x, wid = tid >> 5, lane = tid & 31;
    int bxg = blockIdx.x;
    int z, xbase;
    if (bxg < aa.nbx0) { z = 0; xbase = 0; }
    else if (bxg < aa.nbx0 + aa.nbx1) { z = 1; xbase = aa.nbx0; }
    else { z = 2; xbase = aa.nbx0 + aa.nbx1; }
    const AttnS s = aa.s[z];
    int S = s.S, T = s.T, hasMem = s.hasMem;
    int b = blockIdx.z, h = blockIdx.y, m0 = (bxg - xbase) * 128;
    size_t bh = (size_t)(b * H_ + h);
    const __half* gQ = s.Q + (bh * S + m0) * DHD;
    const __half* gK = s.K + bh * T * DHD;
    const __half* gV = s.V + bh * T * DHD;

    const float SCL2  = 0.088388347648318447f * 1.4426950408889634f;
    const float NEGS2 = -1e9f * 0.088388347648318447f * 1.4426950408889634f;

    // gate row (1+g) for this (b,h), as half2 per 2-column pair
    if (s.gate != nullptr && tid < 64) {
        const float* gp = s.gate + (size_t)b * D_ + h * DHD + tid * 2;
        gh[tid] = __floats2half2_rn(gp[0], gp[1]);
    }

    #pragma unroll
    for (int it = 0; it < 8; it++) {
        int id = tid + it * 256; int row = id >> 4, cc = id & 15;
        cp16(sb + A_Q + row * (APAD * 2) + cc * 16, gQ + row * DHD + cc * 8);
    }
    auto load_kv = [&](int kt, int st2) {
        int t0 = kt * 64;
        uint32_t st = sb + A_ST0 + st2 * A_STG;
        const __half* gm[2] = { gK, gV };
        #pragma unroll
        for (int m = 0; m < 2; m++) {
            #pragma unroll
            for (int it = 0; it < 4; it++) {
                int id = tid + it * 256; int row = id >> 4, cc = id & 15;
                int t = t0 + row;
                int tc = (t < T) ? t : (T - 1);
                int sz = (t < T) ? 16 : 0;
                cp16z(st + m * (64 * APAD * 2) + row * (APAD * 2) + cc * 16,
                      gm[m] + (size_t)tc * DHD + cc * 8, sz);
            }
        }
        if (tid < 64) {
            int t = t0 + tid;
            float bias = NEGS2;
            if (t < T) {
                if (hasMem && t == 0) bias = 0.f;
                else bias = (s.mask[(size_t)b * S + (t - hasMem)] != 0.f) ? 0.f : NEGS2;
            }
            km[st2 * 64 + tid] = bias;
        }
    };

    load_kv(0, 0);
    cp_commit();

    float o[16][4];
    #pragma unroll
    for (int i = 0; i < 16; i++) { o[i][0] = 0.f; o[i][1] = 0.f; o[i][2] = 0.f; o[i][3] = 0.f; }
    float mprev0 = -1e30f, mprev1 = -1e30f, lsum0 = 0.f, lsum1 = 0.f;
    int wm = wid * 16;
    int ntile = (T + 63) / 64;

    for (int kt = 0; kt < ntile; kt++) {
        if (kt + 1 < ntile) { load_kv(kt + 1, (kt + 1) & 1); cp_commit(); cp_wait1(); }
        else cp_wait0();
        __syncthreads();

        // ---- apply gates in smem (Q once, K per tile) ----
        if (s.gate != nullptr) {
            if (kt == 0) {
                int row = tid >> 1, c0 = (tid & 1) << 5;
                __half2* qrow = (__half2*)(smc + A_Q + row * (APAD * 2)) + c0;
                #pragma unroll
                for (int j = 0; j < 32; j++) qrow[j] = __hmul2(qrow[j], gh[c0 + j]);
            }
            {
                int row = tid >> 2, c0 = (tid & 3) << 4;
                __half2* krow = (__half2*)(smc + A_ST0 + (kt & 1) * A_STG + A_K
                                           + row * (APAD * 2)) + c0;
                #pragma unroll
                for (int j = 0; j < 16; j++) krow[j] = __hmul2(krow[j], gh[c0 + j]);
            }
            __syncthreads();
        }
        uint32_t st = sb + A_ST0 + (kt & 1) * A_STG;

        float sf[8][4];
        #pragma unroll
        for (int i = 0; i < 8; i++) { sf[i][0]=0.f; sf[i][1]=0.f; sf[i][2]=0.f; sf[i][3]=0.f; }
        #pragma unroll
        for (int ks = 0; ks < 128; ks += 16) {
            int arow = wm + (lane & 15), ak = ks + ((lane >> 4) << 3);
            uint32_t ah[4];
            ldmx4(ah, sb + A_Q + (uint32_t)(arow * APAD + ak) * 2);
            int r = lane & 7, qs = lane >> 3;
            #pragma unroll
            for (int pr = 0; pr < 4; pr++) {
                int nn = pr * 16 + ((qs >> 1) << 3) + r;
                int kk2 = ks + ((qs & 1) << 3);
                uint32_t bh4[4];
                ldmx4(bh4, st + A_K + (uint32_t)(nn * APAD + kk2) * 2);
                mma16816(sf[pr * 2 + 0], ah, bh4[0], bh4[1]);
                mma16816(sf[pr * 2 + 1], ah, bh4[2], bh4[3]);
            }
        }
        const float* kmc = km + (kt & 1) * 64;
        float mx0 = mprev0, mx1 = mprev1;
        #pragma unroll
        for (int nt = 0; nt < 8; nt++) {
            int c0 = nt * 8 + ((lane & 3) << 1);
            float kb0 = kmc[c0], kb1 = kmc[c0 + 1];
            sf[nt][0] = fmaf(sf[nt][0], SCL2, kb0);
            sf[nt][1] = fmaf(sf[nt][1], SCL2, kb1);
            sf[nt][2] = fmaf(sf[nt][2], SCL2, kb0);
            sf[nt][3] = fmaf(sf[nt][3], SCL2, kb1);
            mx0 = fmaxf(mx0, fmaxf(sf[nt][0], sf[nt][1]));
            mx1 = fmaxf(mx1, fmaxf(sf[nt][2], sf[nt][3]));
        }
        mx0 = fmaxf(mx0, __shfl_xor_sync(0xffffffffu, mx0, 1));
        mx0 = fmaxf(mx0, __shfl_xor_sync(0xffffffffu, mx0, 2));
        mx1 = fmaxf(mx1, __shfl_xor_sync(0xffffffffu, mx1, 1));
        mx1 = fmaxf(mx1, __shfl_xor_sync(0xffffffffu, mx1, 2));
        float corr0 = exp2f(mprev0 - mx0), corr1 = exp2f(mprev1 - mx1);
        mprev0 = mx0; mprev1 = mx1;
        float ps0 = 0.f, ps1 = 0.f;
        #pragma unroll
        for (int nt = 0; nt < 8; nt++) {
            sf[nt][0] = exp2f(sf[nt][0] - mx0);
            sf[nt][1] = exp2f(sf[nt][1] - mx0);
            sf[nt][2] = exp2f(sf[nt][2] - mx1);
            sf[nt][3] = exp2f(sf[nt][3] - mx1);
            ps0 += sf[nt][0] + sf[nt][1];
            ps1 += sf[nt][2] + sf[nt][3];
        }
        ps0 += __shfl_xor_sync(0xffffffffu, ps0, 1);
        ps0 += __shfl_xor_sync(0xffffffffu, ps0, 2);
        ps1 += __shfl_xor_sync(0xffffffffu, ps1, 1);
        ps1 += __shfl_xor_sync(0xffffffffu, ps1, 2);
        lsum0 = lsum0 * corr0 + ps0;
        lsum1 = lsum1 * corr1 + ps1;
        #pragma unroll
        for (int dd = 0; dd < 16; dd++) {
            o[dd][0] *= corr0; o[dd][1] *= corr0;
            o[dd][2] *= corr1; o[dd][3] *= corr1;
        }
        int mi = lane >> 3, rr = lane & 7;
        #pragma unroll
        for (int kk = 0; kk < 4; kk++) {
            uint32_t ph4[4];
            ph4[0] = packh2(sf[2*kk][0],   sf[2*kk][1]);
            ph4[1] = packh2(sf[2*kk][2],   sf[2*kk][3]);
            ph4[2] = packh2(sf[2*kk+1][0], sf[2*kk+1][1]);
            ph4[3] = packh2(sf[2*kk+1][2], sf[2*kk+1][3]);
            #pragma unroll
            for (int db = 0; db < 8; db++) {
                uint32_t voff = (uint32_t)((kk * 16 + (mi & 1) * 8 + rr) * APAD
                                           + db * 16 + (mi >> 1) * 8) * 2;
                uint32_t vh4[4];
                ldmx4t(vh4, st + A_V + voff);
                mma16816(o[db * 2],     ph4, vh4[0], vh4[1]);
                mma16816(o[db * 2 + 1], ph4, vh4[2], vh4[3]);
            }
        }
        __syncthreads();
    }

    float i0 = 1.f / lsum0, i1 = 1.f / lsum1;
    int g = lane >> 2;
    size_t row0 = (size_t)(b * S + m0 + wm + g);
    const float* rs0 = s.resid + row0 * D_ + h * DHD;
    size_t ob0 = row0 * D_ + h * DHD;
    #pragma unroll
    for (int dd = 0; dd < 16; dd++) {
        int d = dd * 8 + ((lane & 3) << 1);
        float2 rv0 = *(const float2*)(rs0 + d);
        float2 rv1 = *(const float2*)(rs0 + 8 * D_ + d);
        store_h2(s.outA, ob0 + d,          rv0.x + o[dd][0] * i0, rv0.y + o[dd][1] * i0);
        store_h2(s.outA, ob0 + 8 * D_ + d, rv1.x + o[dd][2] * i1, rv1.y + o[dd][3] * i1);
    }
}

// ---------------- launch ----------------
extern "C" void kernel_launch(void* const* d_in, const int* in_sizes, int n_in,
                              void* d_out, int out_size) {
    const float* v      = (const float*)d_in[0];
    const float* q      = (const float*)d_in[1];
    const float* c      = (const float*)d_in[2];
    const float* v_mask = (const float*)d_in[3];
    const float* q_mask = (const float*)d_in[4];
    const float* c_mask = (const float*)d_in[5];
    const float* Wv4q   = (const float*)d_in[6];
    const float* bv4q   = (const float*)d_in[7];
    const float* Wq4v   = (const float*)d_in[8];
    const float* bq4v   = (const float*)d_in[9];
    const float* Wv     = (const float*)d_in[10];
    const float* bv     = (const float*)d_in[11];
    const float* Wq     = (const float*)d_in[12];
    const float* bq     = (const float*)d_in[13];
    const float* Wc     = (const float*)d_in[14];
    const float* bcin   = (const float*)d_in[15];
    const float* m_v_k  = (const float*)d_in[16];
    const float* m_v_v  = (const float*)d_in[17];
    const float* m_c_k  = (const float*)d_in[18];
    const float* m_c_v  = (const float*)d_in[19];
    const float* Wvo    = (const float*)d_in[20];
    const float* bvo    = (const float*)d_in[21];
    const float* Wqo    = (const float*)d_in[22];
    const float* bqo    = (const float*)d_in[23];
    const float* Wco    = (const float*)d_in[24];
    const float* bco    = (const float*)d_in[25];
    (void)in_sizes; (void)n_in; (void)out_size;

    float *gv4q, *gq4v, *mnv, *mnq;
    __half *a_v, *a_q, *a_c, *wt;
    __half *vK,*vQ,*vV, *qK,*qQ,*qV, *cK,*cQ,*cV;
    cudaGetSymbolAddress((void**)&gv4q,  g_gate_v4q);
    cudaGetSymbolAddress((void**)&gq4v,  g_gate_q4v);
    cudaGetSymbolAddress((void**)&mnv,   g_mean_v);
    cudaGetSymbolAddress((void**)&mnq,   g_mean_q);
    cudaGetSymbolAddress((void**)&a_v,   g_a_v);
    cudaGetSymbolAddress((void**)&a_q,   g_a_q);
    cudaGetSymbolAddress((void**)&a_c,   g_a_c);
    cudaGetSymbolAddress((void**)&wt,    g_wt);
    cudaGetSymbolAddress((void**)&vK, g_vK); cudaGetSymbolAddress((void**)&vQ, g_vQ);
    cudaGetSymbolAddress((void**)&vV, g_vV);
    cudaGetSymbolAddress((void**)&qK, g_qK); cudaGetSymbolAddress((void**)&qQ, g_qQ);
    cudaGetSymbolAddress((void**)&qV, g_qV);
    cudaGetSymbolAddress((void**)&cK, g_cK); cudaGetSymbolAddress((void**)&cQ, g_cQ);
    cudaGetSymbolAddress((void**)&cV, g_cV);

    cudaFuncSetAttribute(mma_gemm_kernel<true, true>,   cudaFuncAttributeMaxDynamicSharedMemorySize, MMA_SMEM_BYTES);
    cudaFuncSetAttribute(mma_gemm_kernel<false, false>, cudaFuncAttributeMaxDynamicSharedMemorySize, MMA_SMEM_BYTES);
    cudaFuncSetAttribute(attn_mma_kernel, cudaFuncAttributeMaxDynamicSharedMemorySize, ATT_SMEM_BYTES);

    static cudaStream_t s1 = nullptr, s2 = nullptr;
    static cudaEvent_t e0 = nullptr, e1 = nullptr, e2 = nullptr;
    if (s1 == nullptr) {
        cudaStreamCreateWithFlags(&s1, cudaStreamNonBlocking);
        cudaStreamCreateWithFlags(&s2, cudaStreamNonBlocking);
        cudaEventCreateWithFlags(&e0, cudaEventDisableTiming);
        cudaEventCreateWithFlags(&e1, cudaEventDisableTiming);
        cudaEventCreateWithFlags(&e2, cudaEventDisableTiming);
    }

    const size_t WO_V = 0, WO_Q = 3145728, WO_C = 6291456;
    const size_t WO_VO = 9437184, WO_QO = 10485760, WO_CO = 11534336;

    // fork: s1 = wT + memtok (attention prereqs), s2 = mean -> gate (QKV no longer
    // depends on gate; its chain hides under the QKV GEMM), main = act -> QKV.
    cudaEventRecord(e0, 0);
    cudaStreamWaitEvent(s1, e0, 0);
    cudaStreamWaitEvent(s2, e0, 0);
    {
        WTArgs wa;
        wa.W[0] = Wv;  wa.out[0] = wt + WO_V;  wa.N[0] = N3;
        wa.W[1] = Wq;  wa.out[1] = wt + WO_Q;  wa.N[1] = N3;
        wa.W[2] = Wc;  wa.out[2] = wt + WO_C;  wa.N[2] = N3;
        wa.W[3] = Wvo; wa.out[3] = wt + WO_VO; wa.N[3] = D_;
        wa.W[4] = Wqo; wa.out[4] = wt + WO_QO; wa.N[4] = D_;
        wa.W[5] = Wco; wa.out[5] = wt + WO_CO; wa.N[5] = D_;
        cvt_wT_kernel<<<dim3(N3 / 32, 32, 6), dim3(32, 8), 0, s1>>>(wa);
    }
    {
        MemArgs me;
        me.K[0] = vK; me.V[0] = vV; me.mk[0] = m_v_k; me.mv[0] = m_v_v; me.T[0] = SV + 1;
        me.K[1] = cK; me.V[1] = cV; me.mk[1] = m_c_k; me.mv[1] = m_c_v; me.T[1] = SC + 1;
        memtok_kernel<<<dim3(B_, 2), 1024, 0, s1>>>(me);
    }
    {
        MeanArgs ma;
        ma.x[0] = v; ma.mask[0] = v_mask; ma.out[0] = mnv; ma.S[0] = SV;
        ma.x[1] = q; ma.mask[1] = q_mask; ma.out[1] = mnq; ma.S[1] = SQ;
        mean_relu_kernel<<<dim3(4, B_, 2), 256, 0, s2>>>(ma);
    }
    {
        GateArgs ga;
        ga.mean[0] = mnv; ga.W[0] = Wv4q; ga.bias[0] = bv4q; ga.out[0] = gv4q;
        ga.mean[1] = mnq; ga.W[1] = Wq4v; ga.bias[1] = bq4v; ga.out[1] = gq4v;
        gate_kernel<<<dim3(8, B_, 2), 512, 0, s2>>>(ga);
    }
    {
        ActArgs aa;
        aa.x[0] = v; aa.out[0] = a_v; aa.nblk0 = 16384;
        aa.x[1] = q; aa.out[1] = a_q; aa.nblk1 = 8192;
        aa.x[2] = c; aa.out[2] = a_c;
        cvt_act_kernel<<<16384 + 8192 + 16384, 256>>>(aa);
    }
    cudaEventRecord(e1, s1);
    cudaEventRecord(e2, s2);
    cudaStreamWaitEvent(0, e1, 0);   // wT + memtok before QKV/attention

    // QKV projections (merged 3 streams; ungated fp16 K/Q/V)
    {
        Gemm3 g3{};
        g3.s[0] = { a_v, wt + WO_V, bv,   v_mask, vK, vQ, vV, nullptr, SV, SV + 1, 1 };
        g3.s[1] = { a_q, wt + WO_Q, bq,   q_mask, qK, qQ, qV, nullptr, SQ, SQ,     0 };
        g3.s[2] = { a_c, wt + WO_C, bcin, c_mask, cK, cQ, cV, nullptr, SC, SC + 1, 1 };
        g3.nby0 = 128; g3.nby1 = 64;
        mma_gemm_kernel<true, true><<<dim3(24, 320), 128, MMA_SMEM_BYTES>>>(g3, N3);
    }
    cudaStreamWaitEvent(0, e2, 0);   // gates ready (computed in QKV's shadow)
    // attention (merged 3 streams; gating applied here)
    {
        Attn3 a3{};
        a3.s[0] = { vK, vQ, vV, v_mask, v, gq4v,    a_v, SV, SV + 1, 1 };
        a3.s[1] = { qK, qQ, qV, q_mask, q, gv4q,    a_q, SQ, SQ,     0 };
        a3.s[2] = { cK, cQ, cV, c_mask, c, nullptr, a_c, SC, SC + 1, 1 };
        a3.nbx0 = SV / 128; a3.nbx1 = SQ / 128;
        attn_mma_kernel<<<dim3(SV / 128 + SQ / 128 + SC / 128, H_, B_), 256, ATT_SMEM_BYTES>>>(a3);
    }
    // output projections (merged 3 streams)
    {
        float* out = (float*)d_out;
        Gemm3 g3{};
        g3.s[0] = { a_v, wt + WO_VO, bvo, nullptr, nullptr, nullptr, nullptr,
                    out, 0, 0, 0 };
        g3.s[1] = { a_q, wt + WO_QO, bqo, nullptr, nullptr, nullptr, nullptr,
                    out + (size_t)B_ * SV * D_, 0, 0, 0 };
        g3.s[2] = { a_c, wt + WO_CO, bco, nullptr, nullptr, nullptr, nullptr,
                    out + (size_t)B_ * (SV + SQ) * D_, 0, 0, 0 };
        g3.nby0 = 128; g3.nby1 = 64;
        mma_gemm_kernel<false, false><<<dim3(8, 320), 128, MMA_SMEM_BYTES>>>(g3, D_);
    }
}

// round 13
// speedup vs baseline: 1.0079x; 1.0079x over previous
#include <cuda_runtime.h>
#include <cuda_fp16.h>
#include <cstdint>

#define B_   32
#define SV   512
#define SQ   256
#define SC   512
#define D_   1024
#define H_   8
#define DHD  128
#define N3   3072
#define GK   1024

// ---------------- scratch (device globals; no allocations allowed) ----------------
__device__ float g_gate_v4q[32768];
__device__ float g_gate_q4v[32768];
__device__ float g_mean_v[32768];
__device__ float g_mean_q[32768];

// fp16 activations + transposed weights for GEMMs
__device__ __half g_a_v[16777216];
__device__ __half g_a_q[8388608];
__device__ __half g_a_c[16777216];
__device__ __half g_wt[12582912];
// offsets: Wv=0, Wq=3145728, Wc=6291456, Wvo=9437184, Wqo=10485760, Wco=11534336

// fp16 K/Q/V in [B,H,T,dh] layout (gates + mask pre-applied; mem token at t=0)
__device__ __half g_vK[16809984], g_vQ[16777216], g_vV[16809984];
__device__ __half g_qK[8388608],  g_qQ[8388608],  g_qV[8388608];
__device__ __half g_cK[16809984], g_cQ[16777216], g_cV[16809984];

// ---------------- base-target tensor helpers ----------------
__device__ __forceinline__ uint32_t smem_u32(const void* p) {
    uint32_t a;
    asm("{ .reg .u64 t; cvta.to.shared.u64 t, %1; cvt.u32.u64 %0, t; }" : "=r"(a) : "l"(p));
    return a;
}
__device__ __forceinline__ void cp16(uint32_t dst, const void* src) {
    asm volatile("cp.async.cg.shared.global [%0], [%1], 16;" :: "r"(dst), "l"(src));
}
__device__ __forceinline__ void cp16z(uint32_t dst, const void* src, int sz) {
    asm volatile("cp.async.cg.shared.global [%0], [%1], 16, %2;" :: "r"(dst), "l"(src), "r"(sz));
}
__device__ __forceinline__ void cp_commit() { asm volatile("cp.async.commit_group;" ::: "memory"); }
__device__ __forceinline__ void cp_wait1()  { asm volatile("cp.async.wait_group 1;" ::: "memory"); }
__device__ __forceinline__ void cp_wait0()  { asm volatile("cp.async.wait_group 0;" ::: "memory"); }

__device__ __forceinline__ void ldmx4(uint32_t* r, uint32_t addr) {
    asm volatile("ldmatrix.sync.aligned.m8n8.x4.shared.b16 {%0,%1,%2,%3}, [%4];"
                 : "=r"(r[0]), "=r"(r[1]), "=r"(r[2]), "=r"(r[3]) : "r"(addr));
}
__device__ __forceinline__ void ldmx4t(uint32_t* r, uint32_t addr) {
    asm volatile("ldmatrix.sync.aligned.m8n8.x4.trans.shared.b16 {%0,%1,%2,%3}, [%4];"
                 : "=r"(r[0]), "=r"(r[1]), "=r"(r[2]), "=r"(r[3]) : "r"(addr));
}
__device__ __forceinline__ void mma16816(float* d, const uint32_t* a, uint32_t b0, uint32_t b1) {
    asm volatile("mma.sync.aligned.m16n8k16.row.col.f32.f16.f16.f32 "
                 "{%0,%1,%2,%3}, {%4,%5,%6,%7}, {%8,%9}, {%0,%1,%2,%3};"
                 : "+f"(d[0]), "+f"(d[1]), "+f"(d[2]), "+f"(d[3])
                 : "r"(a[0]), "r"(a[1]), "r"(a[2]), "r"(a[3]), "r"(b0), "r"(b1));
}

// ---------------- fp16 pack helpers ----------------
__device__ __forceinline__ uint32_t packh2(float x, float y) {
    __half2 h = __floats2half2_rn(x, y);
    return *(uint32_t*)&h;
}
__device__ __forceinline__ void store_h2(__half* H, size_t idx, float x, float y) {
    *(__half2*)(H + idx) = __floats2half2_rn(x, y);
}

// ---------------- fused conversion kernels ----------------
struct ActArgs { const float* x[3]; __half* out[3]; int nblk0, nblk1; };
__global__ void cvt_act_kernel(ActArgs a) {
    int bx = blockIdx.x;
    int z, base;
    if (bx < a.nblk0) { z = 0; base = 0; }
    else if (bx < a.nblk0 + a.nblk1) { z = 1; base = a.nblk0; }
    else { z = 2; base = a.nblk0 + a.nblk1; }
    int idx = (bx - base) * 256 + threadIdx.x;
    float4 v = ((const float4*)a.x[z])[idx];
    v.x = fmaxf(v.x, 0.f); v.y = fmaxf(v.y, 0.f);
    v.z = fmaxf(v.z, 0.f); v.w = fmaxf(v.w, 0.f);
    uint2 o;
    o.x = packh2(v.x, v.y);
    o.y = packh2(v.z, v.w);
    ((uint2*)a.out[z])[idx] = o;
}

struct WTArgs { const float* W[6]; __half* out[6]; int N[6]; };
__global__ void cvt_wT_kernel(WTArgs a) {
    int z = blockIdx.z;
    const float* W = a.W[z];
    __half* th = a.out[z];
    int N = a.N[z];
    if (blockIdx.x * 32 >= N) return;
    __shared__ float t[32][33];
    int n0 = blockIdx.x * 32, k0 = blockIdx.y * 32;
    int tx = threadIdx.x, ty = threadIdx.y;   // (32, 8)
    #pragma unroll
    for (int r = 0; r < 4; r++)
        t[ty + 8 * r][tx] = W[(size_t)(k0 + ty + 8 * r) * N + n0 + tx];
    __syncthreads();
    #pragma unroll
    for (int r = 0; r < 4; r++) {
        size_t o = (size_t)(n0 + ty + 8 * r) * GK + k0 + tx;
        th[o] = __float2half_rn(t[tx][ty + 8 * r]);
    }
}

// ---------------- small fused kernels ----------------
struct MeanArgs { const float* x[2]; const float* mask[2]; float* out[2]; int S[2]; };
__global__ void mean_relu_kernel(MeanArgs a) {
    __shared__ float red[256];
    __shared__ float sinv;
    int z = blockIdx.z;
    int S = a.S[z];
    int b = blockIdx.y;
    const float* mp = a.mask[z] + (size_t)b * S;
    float s = 0.f;
    for (int t = threadIdx.x; t < S; t += 256) s += mp[t];
    red[threadIdx.x] = s;
    __syncthreads();
    for (int w = 128; w > 0; w >>= 1) {
        if (threadIdx.x < w) red[threadIdx.x] += red[threadIdx.x + w];
        __syncthreads();
    }
    if (threadIdx.x == 0) sinv = 1.f / red[0];
    __syncthreads();
    int d = blockIdx.x * 256 + threadIdx.x;
    const float* xp = a.x[z] + (size_t)b * S * D_ + d;
    float a0 = 0.f, a1 = 0.f, a2 = 0.f, a3 = 0.f;
    for (int t = 0; t < S; t += 4) {
        a0 = fmaf(xp[(size_t)(t + 0) * D_], mp[t + 0], a0);
        a1 = fmaf(xp[(size_t)(t + 1) * D_], mp[t + 1], a1);
        a2 = fmaf(xp[(size_t)(t + 2) * D_], mp[t + 2], a2);
        a3 = fmaf(xp[(size_t)(t + 3) * D_], mp[t + 3], a3);
    }
    a.out[z][b * D_ + d] = fmaxf(((a0 + a1) + (a2 + a3)) * sinv, 0.f);
}

// gate: k-parallel (4 k-groups x 128 n), smem reduce. grid (8, B, 2), block 512.
struct GateArgs { const float* mean[2]; const float* W[2]; const float* bias[2]; float* out[2]; };
__global__ __launch_bounds__(512) void gate_kernel(GateArgs a) {
    __shared__ float sm[D_];
    __shared__ float red[512];
    int z = blockIdx.z;
    int b = blockIdx.y;
    int tid = threadIdx.x;
    int g = tid >> 7;            // k-group 0..3
    int nl = tid & 127;
    const float* rmean = a.mean[z];
    const float* W = a.W[z];
    for (int k = tid; k < D_; k += 512) sm[k] = rmean[b * D_ + k];
    __syncthreads();
    int n = blockIdx.x * 128 + nl;
    int k0 = g * 256;
    float acc = 0.f;
    #pragma unroll 8
    for (int k = 0; k < 256; k++)
        acc = fmaf(sm[k0 + k], W[(size_t)(k0 + k) * D_ + n], acc);
    red[tid] = acc;
    __syncthreads();
    if (g == 0) {
        float t = red[nl] + red[nl + 128] + red[nl + 256] + red[nl + 384] + a.bias[z][n];
        a.out[z][b * D_ + n] = 1.f + 1.f / (1.f + __expf(-t));
    }
}

struct MemArgs { __half* K[2]; __half* V[2]; const float* mk[2]; const float* mv[2];
                 const float* gate[2]; int T[2]; };
__global__ void memtok_kernel(MemArgs a) {
    int z = blockIdx.y;
    int b = blockIdx.x;
    int i = threadIdx.x;
    int h = i >> 7;
    float kv = 32.f * a.mk[z][i];
    if (a.gate[z]) kv *= a.gate[z][b * D_ + i];
    size_t idx = ((size_t)(b * H_ + h) * a.T[z]) * DHD + (i & 127);
    a.K[z][idx] = __float2half_rn(kv);
    a.V[z][idx] = __float2half_rn(a.mv[z][i]);
}

// ---------------- mma.sync fp16 GEMM (3-stream merged, BK=64, 2-stage) ----------------
#define ROWB 72                              // 64 halves + pad (144B stride, conflict-free)
#define MAT_BYTES (128 * ROWB * 2)           // 18432
#define STAGE_BYTES (2 * MAT_BYTES)          // 36864
#define MMA_SMEM_BYTES (2 * STAGE_BYTES)     // 73728

struct GemmS {
    const __half *A, *B;
    const float *bias, *mask, *gate;
    __half *oK, *oQ, *oV;
    float* C;
    int S, T, hasMem;
};
struct Gemm3 { GemmS s[3]; int nby0, nby1; };

template <bool MASK, bool SPLIT>
__global__ __launch_bounds__(128, 2) void mma_gemm_kernel(Gemm3 ga, int N)
{
    extern __shared__ char smem[];
    uint32_t sbase = smem_u32(smem);
    int tid = threadIdx.x;
    int wid = tid >> 5, lane = tid & 31;
    int byg = blockIdx.y;
    int z, ybase;
    if (byg < ga.nby0) { z = 0; ybase = 0; }
    else if (byg < ga.nby0 + ga.nby1) { z = 1; ybase = ga.nby0; }
    else { z = 2; ybase = ga.nby0 + ga.nby1; }
    const GemmS s = ga.s[z];
    int bm = (byg - ybase) * 128, bn = blockIdx.x * 128;
    int wm = (wid & 1) * 64;
    int wn = (wid >> 1) * 64;

    const __half* srcs[2] = { s.A + (size_t)bm * GK, s.B + (size_t)bn * GK };

    float acc[4][8][4];
    #pragma unroll
    for (int i = 0; i < 4; i++)
        #pragma unroll
        for (int j = 0; j < 8; j++)
            #pragma unroll
            for (int k = 0; k < 4; k++) acc[i][j][k] = 0.f;

    int lrow = tid >> 3, lc = tid & 7;   // 16 rows x 8 chunks of 16B per pass
    auto load_stage = [&](int kc, int st2) {
        uint32_t st = sbase + st2 * STAGE_BYTES;
        int k0 = kc * 64;
        #pragma unroll
        for (int m = 0; m < 2; m++) {
            const __half* src = srcs[m];
            uint32_t dst = st + m * MAT_BYTES;
            #pragma unroll
            for (int it = 0; it < 8; it++) {
                int row = lrow + it * 16;
                cp16(dst + row * (ROWB * 2) + lc * 16, src + (size_t)row * GK + k0 + lc * 8);
            }
        }
        cp_commit();
    };

    load_stage(0, 0);

    const int NK = GK / 64;   // 16
    for (int kc = 0; kc < NK; kc++) {
        if (kc + 1 < NK) { load_stage(kc + 1, (kc + 1) & 1); cp_wait1(); }
        else cp_wait0();
        __syncthreads();
        uint32_t st = sbase + (kc & 1) * STAGE_BYTES;
        uint32_t sA = st, sB = st + MAT_BYTES;
        #pragma unroll
        for (int ks = 0; ks < 64; ks += 16) {
            uint32_t ah[4][4];
            int arow = wm + (lane & 15);
            int ak = ks + ((lane >> 4) << 3);
            #pragma unroll
            for (int mt = 0; mt < 4; mt++)
                ldmx4(ah[mt], sA + (uint32_t)(((arow + mt * 16) * ROWB + ak) * 2));
            int r = lane & 7, qsel = lane >> 3;
            #pragma unroll
            for (int nt = 0; nt < 4; nt++) {
                int nn = wn + nt * 16 + ((qsel >> 1) << 3) + r;
                int kk = ks + ((qsel & 1) << 3);
                uint32_t bh[4];
                ldmx4(bh, sB + (uint32_t)((nn * ROWB + kk) * 2));
                #pragma unroll
                for (int mt = 0; mt < 4; mt++) {
                    mma16816(acc[mt][nt * 2 + 0], ah[mt], bh[0], bh[1]);
                    mma16816(acc[mt][nt * 2 + 1], ah[mt], bh[2], bh[3]);
                }
            }
        }
        __syncthreads();
    }

    if (!SPLIT) {
        #pragma unroll
        for (int mt = 0; mt < 4; mt++) {
            int r0 = bm + wm + mt * 16 + (lane >> 2);
            float m0 = MASK ? s.mask[r0] : 1.f;
            float m1 = MASK ? s.mask[r0 + 8] : 1.f;
            #pragma unroll
            for (int nt = 0; nt < 8; nt++) {
                int col = bn + wn + nt * 8 + ((lane & 3) << 1);
                float2 bb = *(const float2*)&s.bias[col];
                float2 o0, o1;
                o0.x = (acc[mt][nt][0] + bb.x) * m0; o0.y = (acc[mt][nt][1] + bb.y) * m0;
                o1.x = (acc[mt][nt][2] + bb.x) * m1; o1.y = (acc[mt][nt][3] + bb.y) * m1;
                *(float2*)(s.C + (size_t)r0 * N + col) = o0;
                *(float2*)(s.C + (size_t)(r0 + 8) * N + col) = o1;
            }
        }
    } else {
        int colbase = bn + wn;
        int part = colbase >> 10;           // 0=k, 1=q, 2=v
        int hh = (colbase & 1023) >> 7;
        int dwarp = colbase & 127;
        int b = bm / s.S;
        int s0 = bm % s.S;
        size_t bh64 = (size_t)(b * H_ + hh);
        #pragma unroll
        for (int mt = 0; mt < 4; mt++) {
            int rl0 = wm + mt * 16 + (lane >> 2);
            int gr0 = bm + rl0;
            float mk0 = MASK ? s.mask[gr0] : 1.f;
            float mk1 = MASK ? s.mask[gr0 + 8] : 1.f;
            int s_0 = s0 + rl0, s_1 = s_0 + 8;
            #pragma unroll
            for (int nt = 0; nt < 8; nt++) {
                int d = dwarp + nt * 8 + ((lane & 3) << 1);
                int col = colbase + nt * 8 + ((lane & 3) << 1);
                float2 bb = *(const float2*)&s.bias[col];
                float x0 = (acc[mt][nt][0] + bb.x) * mk0;
                float y0 = (acc[mt][nt][1] + bb.y) * mk0;
                float x1 = (acc[mt][nt][2] + bb.x) * mk1;
                float y1 = (acc[mt][nt][3] + bb.y) * mk1;
                if (s.gate != nullptr && part < 2) {
                    float2 g2 = *(const float2*)&s.gate[b * D_ + hh * DHD + d];
                    x0 *= g2.x; y0 *= g2.y; x1 *= g2.x; y1 *= g2.y;
                }
                if (part == 0) {
                    store_h2(s.oK, (bh64 * s.T + (s_0 + s.hasMem)) * DHD + d, x0, y0);
                    store_h2(s.oK, (bh64 * s.T + (s_1 + s.hasMem)) * DHD + d, x1, y1);
                } else if (part == 1) {
                    store_h2(s.oQ, (bh64 * s.S + s_0) * DHD + d, x0, y0);
                    store_h2(s.oQ, (bh64 * s.S + s_1) * DHD + d, x1, y1);
                } else {
                    store_h2(s.oV, (bh64 * s.T + (s_0 + s.hasMem)) * DHD + d, x0, y0);
                    store_h2(s.oV, (bh64 * s.T + (s_1 + s.hasMem)) * DHD + d, x1, y1);
                }
            }
        }
    }
}

// ---------------- tensor-core flash attention (fp16, 3-stream merged, exp2) ----------------
#define APAD 136
constexpr int A_Q   = 0;
constexpr int A_ST0 = 128 * APAD * 2;
constexpr int A_STG = 2 * 64 * APAD * 2;
constexpr int A_K   = 0;
constexpr int A_V   = 64 * APAD * 2;
constexpr int A_KM  = A_ST0 + 2 * A_STG;
constexpr int ATT_SMEM_BYTES = A_KM + 2 * 64 * 4;

struct AttnS {
    const __half *K, *Q, *V;
    const float *mask, *resid;
    __half* outA;
    int S, T, hasMem;
};
struct Attn3 { AttnS s[3]; int nbx0, nbx1; };

__global__ __launch_bounds__(256, 2) void attn_mma_kernel(Attn3 aa)
{
    extern __shared__ char sm[];
    uint32_t sb = smem_u32(sm);
    float* km = (float*)(sm + A_KM);
    int tid = threadIdx.x, wid = tid >> 5, lane = tid & 31;
    int bxg = blockIdx.x;
    int z, xbase;
    if (bxg < aa.nbx0) { z = 0; xbase = 0; }
    else if (bxg < aa.nbx0 + aa.nbx1) { z = 1; xbase = aa.nbx0; }
    else { z = 2; xbase = aa.nbx0 + aa.nbx1; }
    const AttnS s = aa.s[z];
    int S = s.S, T = s.T, hasMem = s.hasMem;
    int b = blockIdx.z, h = blockIdx.y, m0 = (bxg - xbase) * 128;
    size_t bh = (size_t)(b * H_ + h);
    const __half* gQ = s.Q + (bh * S + m0) * DHD;
    const __half* gK = s.K + bh * T * DHD;
    const __half* gV = s.V + bh * T * DHD;

    const float SCL2  = 0.088388347648318447f * 1.4426950408889634f;
    const float NEGS2 = -1e9f * 0.088388347648318447f * 1.4426950408889634f;

    #pragma unroll
    for (int it = 0; it < 8; it++) {
        int id = tid + it * 256; int row = id >> 4, cc = id & 15;
        cp16(sb + A_Q + row * (APAD * 2) + cc * 16, gQ + row * DHD + cc * 8);
    }
    auto load_kv = [&](int kt, int st2) {
        int t0 = kt * 64;
        uint32_t st = sb + A_ST0 + st2 * A_STG;
        const __half* gm[2] = { gK, gV };
        #pragma unroll
        for (int m = 0; m < 2; m++) {
            #pragma unroll
            for (int it = 0; it < 4; it++) {
                int id = tid + it * 256; int row = id >> 4, cc = id & 15;
                int t = t0 + row;
                int tc = (t < T) ? t : (T - 1);
                int sz = (t < T) ? 16 : 0;
                cp16z(st + m * (64 * APAD * 2) + row * (APAD * 2) + cc * 16,
                      gm[m] + (size_t)tc * DHD + cc * 8, sz);
            }
        }
        if (tid < 64) {
            int t = t0 + tid;
            float bias = NEGS2;
            if (t < T) {
                if (hasMem && t == 0) bias = 0.f;
                else bias = (s.mask[(size_t)b * S + (t - hasMem)] != 0.f) ? 0.f : NEGS2;
            }
            km[st2 * 64 + tid] = bias;
        }
    };

    load_kv(0, 0);
    cp_commit();

    float o[16][4];
    #pragma unroll
    for (int i = 0; i < 16; i++) { o[i][0] = 0.f; o[i][1] = 0.f; o[i][2] = 0.f; o[i][3] = 0.f; }
    float mprev0 = -1e30f, mprev1 = -1e30f, lsum0 = 0.f, lsum1 = 0.f;
    int wm = wid * 16;
    int ntile = (T + 63) / 64;

    for (int kt = 0; kt < ntile; kt++) {
        if (kt + 1 < ntile) { load_kv(kt + 1, (kt + 1) & 1); cp_commit(); cp_wait1(); }
        else cp_wait0();
        __syncthreads();
        uint32_t st = sb + A_ST0 + (kt & 1) * A_STG;

        float sf[8][4];
        #pragma unroll
        for (int i = 0; i < 8; i++) { sf[i][0]=0.f; sf[i][1]=0.f; sf[i][2]=0.f; sf[i][3]=0.f; }
        #pragma unroll
        for (int ks = 0; ks < 128; ks += 16) {
            int arow = wm + (lane & 15), ak = ks + ((lane >> 4) << 3);
            uint32_t ah[4];
            ldmx4(ah, sb + A_Q + (uint32_t)(arow * APAD + ak) * 2);
            int r = lane & 7, qs = lane >> 3;
            #pragma unroll
            for (int pr = 0; pr < 4; pr++) {
                int nn = pr * 16 + ((qs >> 1) << 3) + r;
                int kk2 = ks + ((qs & 1) << 3);
                uint32_t bh4[4];
                ldmx4(bh4, st + A_K + (uint32_t)(nn * APAD + kk2) * 2);
                mma16816(sf[pr * 2 + 0], ah, bh4[0], bh4[1]);
                mma16816(sf[pr * 2 + 1], ah, bh4[2], bh4[3]);
            }
        }
        const float* kmc = km + (kt & 1) * 64;
        float mx0 = mprev0, mx1 = mprev1;
        #pragma unroll
        for (int nt = 0; nt < 8; nt++) {
            int c0 = nt * 8 + ((lane & 3) << 1);
            float kb0 = kmc[c0], kb1 = kmc[c0 + 1];
            sf[nt][0] = fmaf(sf[nt][0], SCL2, kb0);
            sf[nt][1] = fmaf(sf[nt][1], SCL2, kb1);
            sf[nt][2] = fmaf(sf[nt][2], SCL2, kb0);
            sf[nt][3] = fmaf(sf[nt][3], SCL2, kb1);
            mx0 = fmaxf(mx0, fmaxf(sf[nt][0], sf[nt][1]));
            mx1 = fmaxf(mx1, fmaxf(sf[nt][2], sf[nt][3]));
        }
        mx0 = fmaxf(mx0, __shfl_xor_sync(0xffffffffu, mx0, 1));
        mx0 = fmaxf(mx0, __shfl_xor_sync(0xffffffffu, mx0, 2));
        mx1 = fmaxf(mx1, __shfl_xor_sync(0xffffffffu, mx1, 1));
        mx1 = fmaxf(mx1, __shfl_xor_sync(0xffffffffu, mx1, 2));
        float corr0 = exp2f(mprev0 - mx0), corr1 = exp2f(mprev1 - mx1);
        mprev0 = mx0; mprev1 = mx1;
        float ps0 = 0.f, ps1 = 0.f;
        #pragma unroll
        for (int nt = 0; nt < 8; nt++) {
            sf[nt][0] = exp2f(sf[nt][0] - mx0);
            sf[nt][1] = exp2f(sf[nt][1] - mx0);
            sf[nt][2] = exp2f(sf[nt][2] - mx1);
            sf[nt][3] = exp2f(sf[nt][3] - mx1);
            ps0 += sf[nt][0] + sf[nt][1];
            ps1 += sf[nt][2] + sf[nt][3];
        }
        ps0 += __shfl_xor_sync(0xffffffffu, ps0, 1);
        ps0 += __shfl_xor_sync(0xffffffffu, ps0, 2);
        ps1 += __shfl_xor_sync(0xffffffffu, ps1, 1);
        ps1 += __shfl_xor_sync(0xffffffffu, ps1, 2);
        lsum0 = lsum0 * corr0 + ps0;
        lsum1 = lsum1 * corr1 + ps1;
        if (kt > 0) {
            #pragma unroll
            for (int dd = 0; dd < 16; dd++) {
                o[dd][0] *= corr0; o[dd][1] *= corr0;
                o[dd][2] *= corr1; o[dd][3] *= corr1;
            }
        }
        int mi = lane >> 3, rr = lane & 7;
        #pragma unroll
        for (int kk = 0; kk < 4; kk++) {
            uint32_t ph4[4];
            ph4[0] = packh2(sf[2*kk][0],   sf[2*kk][1]);
            ph4[1] = packh2(sf[2*kk][2],   sf[2*kk][3]);
            ph4[2] = packh2(sf[2*kk+1][0], sf[2*kk+1][1]);
            ph4[3] = packh2(sf[2*kk+1][2], sf[2*kk+1][3]);
            #pragma unroll
            for (int db = 0; db < 8; db++) {
                uint32_t voff = (uint32_t)((kk * 16 + (mi & 1) * 8 + rr) * APAD
                                           + db * 16 + (mi >> 1) * 8) * 2;
                uint32_t vh4[4];
                ldmx4t(vh4, st + A_V + voff);
                mma16816(o[db * 2],     ph4, vh4[0], vh4[1]);
                mma16816(o[db * 2 + 1], ph4, vh4[2], vh4[3]);
            }
        }
        __syncthreads();
    }

    float i0 = 1.f / lsum0, i1 = 1.f / lsum1;
    int g = lane >> 2;
    size_t row0 = (size_t)(b * S + m0 + wm + g);
    const float* rs0 = s.resid + row0 * D_ + h * DHD;
    size_t ob0 = row0 * D_ + h * DHD;
    #pragma unroll
    for (int dd = 0; dd < 16; dd++) {
        int d = dd * 8 + ((lane & 3) << 1);
        float2 rv0 = *(const float2*)(rs0 + d);
        float2 rv1 = *(const float2*)(rs0 + 8 * D_ + d);
        store_h2(s.outA, ob0 + d,          rv0.x + o[dd][0] * i0, rv0.y + o[dd][1] * i0);
        store_h2(s.outA, ob0 + 8 * D_ + d, rv1.x + o[dd][2] * i1, rv1.y + o[dd][3] * i1);
    }
}

// ---------------- launch ----------------
extern "C" void kernel_launch(void* const* d_in, const int* in_sizes, int n_in,
                              void* d_out, int out_size) {
    const float* v      = (const float*)d_in[0];
    const float* q      = (const float*)d_in[1];
    const float* c      = (const float*)d_in[2];
    const float* v_mask = (const float*)d_in[3];
    const float* q_mask = (const float*)d_in[4];
    const float* c_mask = (const float*)d_in[5];
    const float* Wv4q   = (const float*)d_in[6];
    const float* bv4q   = (const float*)d_in[7];
    const float* Wq4v   = (const float*)d_in[8];
    const float* bq4v   = (const float*)d_in[9];
    const float* Wv     = (const float*)d_in[10];
    const float* bv     = (const float*)d_in[11];
    const float* Wq     = (const float*)d_in[12];
    const float* bq     = (const float*)d_in[13];
    const float* Wc     = (const float*)d_in[14];
    const float* bcin   = (const float*)d_in[15];
    const float* m_v_k  = (const float*)d_in[16];
    const float* m_v_v  = (const float*)d_in[17];
    const float* m_c_k  = (const float*)d_in[18];
    const float* m_c_v  = (const float*)d_in[19];
    const float* Wvo    = (const float*)d_in[20];
    const float* bvo    = (const float*)d_in[21];
    const float* Wqo    = (const float*)d_in[22];
    const float* bqo    = (const float*)d_in[23];
    const float* Wco    = (const float*)d_in[24];
    const float* bco    = (const float*)d_in[25];
    (void)in_sizes; (void)n_in; (void)out_size;

    float *gv4q, *gq4v, *mnv, *mnq;
    __half *a_v, *a_q, *a_c, *wt;
    __half *vK,*vQ,*vV, *qK,*qQ,*qV, *cK,*cQ,*cV;
    cudaGetSymbolAddress((void**)&gv4q,  g_gate_v4q);
    cudaGetSymbolAddress((void**)&gq4v,  g_gate_q4v);
    cudaGetSymbolAddress((void**)&mnv,   g_mean_v);
    cudaGetSymbolAddress((void**)&mnq,   g_mean_q);
    cudaGetSymbolAddress((void**)&a_v,   g_a_v);
    cudaGetSymbolAddress((void**)&a_q,   g_a_q);
    cudaGetSymbolAddress((void**)&a_c,   g_a_c);
    cudaGetSymbolAddress((void**)&wt,    g_wt);
    cudaGetSymbolAddress((void**)&vK, g_vK); cudaGetSymbolAddress((void**)&vQ, g_vQ);
    cudaGetSymbolAddress((void**)&vV, g_vV);
    cudaGetSymbolAddress((void**)&qK, g_qK); cudaGetSymbolAddress((void**)&qQ, g_qQ);
    cudaGetSymbolAddress((void**)&qV, g_qV);
    cudaGetSymbolAddress((void**)&cK, g_cK); cudaGetSymbolAddress((void**)&cQ, g_cQ);
    cudaGetSymbolAddress((void**)&cV, g_cV);

    cudaFuncSetAttribute(mma_gemm_kernel<true, true>,   cudaFuncAttributeMaxDynamicSharedMemorySize, MMA_SMEM_BYTES);
    cudaFuncSetAttribute(mma_gemm_kernel<false, false>, cudaFuncAttributeMaxDynamicSharedMemorySize, MMA_SMEM_BYTES);
    cudaFuncSetAttribute(attn_mma_kernel, cudaFuncAttributeMaxDynamicSharedMemorySize, ATT_SMEM_BYTES);

    static cudaStream_t s1 = nullptr, s2 = nullptr;
    static cudaEvent_t e0 = nullptr, e1 = nullptr, e2 = nullptr;
    if (s1 == nullptr) {
        cudaStreamCreateWithFlags(&s1, cudaStreamNonBlocking);
        cudaStreamCreateWithFlags(&s2, cudaStreamNonBlocking);
        cudaEventCreateWithFlags(&e0, cudaEventDisableTiming);
        cudaEventCreateWithFlags(&e1, cudaEventDisableTiming);
        cudaEventCreateWithFlags(&e2, cudaEventDisableTiming);
    }

    const size_t WO_V = 0, WO_Q = 3145728, WO_C = 6291456;
    const size_t WO_VO = 9437184, WO_QO = 10485760, WO_CO = 11534336;

    // fork prologue (R11 schedule): s1 = wT, s2 = act, main = mean->gate->memtok
    cudaEventRecord(e0, 0);
    cudaStreamWaitEvent(s1, e0, 0);
    cudaStreamWaitEvent(s2, e0, 0);
    {
        WTArgs wa;
        wa.W[0] = Wv;  wa.out[0] = wt + WO_V;  wa.N[0] = N3;
        wa.W[1] = Wq;  wa.out[1] = wt + WO_Q;  wa.N[1] = N3;
        wa.W[2] = Wc;  wa.out[2] = wt + WO_C;  wa.N[2] = N3;
        wa.W[3] = Wvo; wa.out[3] = wt + WO_VO; wa.N[3] = D_;
        wa.W[4] = Wqo; wa.out[4] = wt + WO_QO; wa.N[4] = D_;
        wa.W[5] = Wco; wa.out[5] = wt + WO_CO; wa.N[5] = D_;
        cvt_wT_kernel<<<dim3(N3 / 32, 32, 6), dim3(32, 8), 0, s1>>>(wa);
    }
    {
        ActArgs aa;
        aa.x[0] = v; aa.out[0] = a_v; aa.nblk0 = 16384;
        aa.x[1] = q; aa.out[1] = a_q; aa.nblk1 = 8192;
        aa.x[2] = c; aa.out[2] = a_c;
        cvt_act_kernel<<<16384 + 8192 + 16384, 256, 0, s2>>>(aa);
    }
    {
        MeanArgs ma;
        ma.x[0] = v; ma.mask[0] = v_mask; ma.out[0] = mnv; ma.S[0] = SV;
        ma.x[1] = q; ma.mask[1] = q_mask; ma.out[1] = mnq; ma.S[1] = SQ;
        mean_relu_kernel<<<dim3(4, B_, 2), 256>>>(ma);
    }
    {
        GateArgs ga;
        ga.mean[0] = mnv; ga.W[0] = Wv4q; ga.bias[0] = bv4q; ga.out[0] = gv4q;
        ga.mean[1] = mnq; ga.W[1] = Wq4v; ga.bias[1] = bq4v; ga.out[1] = gq4v;
        gate_kernel<<<dim3(8, B_, 2), 512>>>(ga);
    }
    {
        MemArgs me;
        me.K[0] = vK; me.V[0] = vV; me.mk[0] = m_v_k; me.mv[0] = m_v_v;
        me.gate[0] = gq4v; me.T[0] = SV + 1;
        me.K[1] = cK; me.V[1] = cV; me.mk[1] = m_c_k; me.mv[1] = m_c_v;
        me.gate[1] = nullptr; me.T[1] = SC + 1;
        memtok_kernel<<<dim3(B_, 2), 1024>>>(me);
    }
    cudaEventRecord(e1, s1);
    cudaEventRecord(e2, s2);
    cudaStreamWaitEvent(0, e1, 0);
    cudaStreamWaitEvent(0, e2, 0);

    // QKV projections (merged 3 streams)
    {
        Gemm3 g3{};
        g3.s[0] = { a_v, wt + WO_V, bv,   v_mask, gq4v, vK, vQ, vV, nullptr, SV, SV + 1, 1 };
        g3.s[1] = { a_q, wt + WO_Q, bq,   q_mask, gv4q, qK, qQ, qV, nullptr, SQ, SQ,     0 };
        g3.s[2] = { a_c, wt + WO_C, bcin, c_mask, nullptr, cK, cQ, cV, nullptr, SC, SC + 1, 1 };
        g3.nby0 = 128; g3.nby1 = 64;
        mma_gemm_kernel<true, true><<<dim3(24, 320), 128, MMA_SMEM_BYTES>>>(g3, N3);
    }
    // attention (merged 3 streams)
    {
        Attn3 a3{};
        a3.s[0] = { vK, vQ, vV, v_mask, v, a_v, SV, SV + 1, 1 };
        a3.s[1] = { qK, qQ, qV, q_mask, q, a_q, SQ, SQ,     0 };
        a3.s[2] = { cK, cQ, cV, c_mask, c, a_c, SC, SC + 1, 1 };
        a3.nbx0 = SV / 128; a3.nbx1 = SQ / 128;
        attn_mma_kernel<<<dim3(SV / 128 + SQ / 128 + SC / 128, H_, B_), 256, ATT_SMEM_BYTES>>>(a3);
    }
    // output projections (merged 3 streams)
    {
        float* out = (float*)d_out;
        Gemm3 g3{};
        g3.s[0] = { a_v, wt + WO_VO, bvo, nullptr, nullptr, nullptr, nullptr, nullptr,
                    out, 0, 0, 0 };
        g3.s[1] = { a_q, wt + WO_QO, bqo, nullptr, nullptr, nullptr, nullptr, nullptr,
                    out + (size_t)B_ * SV * D_, 0, 0, 0 };
        g3.s[2] = { a_c, wt + WO_CO, bco, nullptr, nullptr, nullptr, nullptr, nullptr,
                    out + (size_t)B_ * (SV + SQ) * D_, 0, 0, 0 };
        g3.nby0 = 128; g3.nby1 = 64;
        mma_gemm_kernel<false, false><<<dim3(8, 320), 128, MMA_SMEM_BYTES>>>(g3, D_);
    }
}

// round 15
// speedup vs baseline: 1.0210x; 1.0129x over previous
#include <cuda_runtime.h>
#include <cuda_fp16.h>
#include <cstdint>

#define B_   32
#define SV   512
#define SQ   256
#define SC   512
#define D_   1024
#define H_   8
#define DHD  128
#define N3   3072
#define GK   1024

// ---------------- scratch (device globals; no allocations allowed) ----------------
__device__ float g_gate_v4q[32768];
__device__ float g_gate_q4v[32768];
__device__ float g_mean_v[32768];
__device__ float g_mean_q[32768];

// fp16 activations + transposed weights for GEMMs
__device__ __half g_a_v[16777216];
__device__ __half g_a_q[8388608];
__device__ __half g_a_c[16777216];
__device__ __half g_wt[12582912];
// offsets: Wv=0, Wq=3145728, Wc=6291456, Wvo=9437184, Wqo=10485760, Wco=11534336

// fp16 K/Q/V in [B,H,T,dh] layout (gates + mask pre-applied; mem token at t=0)
__device__ __half g_vK[16809984], g_vQ[16777216], g_vV[16809984];
__device__ __half g_qK[8388608],  g_qQ[8388608],  g_qV[8388608];
__device__ __half g_cK[16809984], g_cQ[16777216], g_cV[16809984];

// ---------------- base-target tensor helpers ----------------
__device__ __forceinline__ uint32_t smem_u32(const void* p) {
    uint32_t a;
    asm("{ .reg .u64 t; cvta.to.shared.u64 t, %1; cvt.u32.u64 %0, t; }" : "=r"(a) : "l"(p));
    return a;
}
__device__ __forceinline__ void cp16(uint32_t dst, const void* src) {
    asm volatile("cp.async.cg.shared.global [%0], [%1], 16;" :: "r"(dst), "l"(src));
}
__device__ __forceinline__ void cp16z(uint32_t dst, const void* src, int sz) {
    asm volatile("cp.async.cg.shared.global [%0], [%1], 16, %2;" :: "r"(dst), "l"(src), "r"(sz));
}
__device__ __forceinline__ void cp_commit() { asm volatile("cp.async.commit_group;" ::: "memory"); }
__device__ __forceinline__ void cp_wait1()  { asm volatile("cp.async.wait_group 1;" ::: "memory"); }
__device__ __forceinline__ void cp_wait0()  { asm volatile("cp.async.wait_group 0;" ::: "memory"); }

__device__ __forceinline__ void ldmx4(uint32_t* r, uint32_t addr) {
    asm volatile("ldmatrix.sync.aligned.m8n8.x4.shared.b16 {%0,%1,%2,%3}, [%4];"
                 : "=r"(r[0]), "=r"(r[1]), "=r"(r[2]), "=r"(r[3]) : "r"(addr));
}
__device__ __forceinline__ void ldmx4t(uint32_t* r, uint32_t addr) {
    asm volatile("ldmatrix.sync.aligned.m8n8.x4.trans.shared.b16 {%0,%1,%2,%3}, [%4];"
                 : "=r"(r[0]), "=r"(r[1]), "=r"(r[2]), "=r"(r[3]) : "r"(addr));
}
__device__ __forceinline__ void mma16816(float* d, const uint32_t* a, uint32_t b0, uint32_t b1) {
    asm volatile("mma.sync.aligned.m16n8k16.row.col.f32.f16.f16.f32 "
                 "{%0,%1,%2,%3}, {%4,%5,%6,%7}, {%8,%9}, {%0,%1,%2,%3};"
                 : "+f"(d[0]), "+f"(d[1]), "+f"(d[2]), "+f"(d[3])
                 : "r"(a[0]), "r"(a[1]), "r"(a[2]), "r"(a[3]), "r"(b0), "r"(b1));
}
// two exps in one MUFU op; output is the fp16x2 P fragment directly
__device__ __forceinline__ uint32_t h2exp2_u32(float x, float y) {
    __half2 h = __floats2half2_rn(x, y);
    uint32_t r;
    asm("ex2.approx.f16x2 %0, %1;" : "=r"(r) : "r"(*(uint32_t*)&h));
    return r;
}

// ---------------- fp16 pack helpers ----------------
__device__ __forceinline__ uint32_t packh2(float x, float y) {
    __half2 h = __floats2half2_rn(x, y);
    return *(uint32_t*)&h;
}
__device__ __forceinline__ void store_h2(__half* H, size_t idx, float x, float y) {
    *(__half2*)(H + idx) = __floats2half2_rn(x, y);
}

// ---------------- fused conversion kernels ----------------
struct ActArgs { const float* x[3]; __half* out[3]; int nblk0, nblk1; };
__global__ void cvt_act_kernel(ActArgs a) {
    int bx = blockIdx.x;
    int z, base;
    if (bx < a.nblk0) { z = 0; base = 0; }
    else if (bx < a.nblk0 + a.nblk1) { z = 1; base = a.nblk0; }
    else { z = 2; base = a.nblk0 + a.nblk1; }
    int idx = (bx - base) * 256 + threadIdx.x;
    float4 v = ((const float4*)a.x[z])[idx];
    v.x = fmaxf(v.x, 0.f); v.y = fmaxf(v.y, 0.f);
    v.z = fmaxf(v.z, 0.f); v.w = fmaxf(v.w, 0.f);
    uint2 o;
    o.x = packh2(v.x, v.y);
    o.y = packh2(v.z, v.w);
    ((uint2*)a.out[z])[idx] = o;
}

struct WTArgs { const float* W[6]; __half* out[6]; int N[6]; };
__global__ void cvt_wT_kernel(WTArgs a) {
    int z = blockIdx.z;
    const float* W = a.W[z];
    __half* th = a.out[z];
    int N = a.N[z];
    if (blockIdx.x * 32 >= N) return;
    __shared__ float t[32][33];
    int n0 = blockIdx.x * 32, k0 = blockIdx.y * 32;
    int tx = threadIdx.x, ty = threadIdx.y;   // (32, 8)
    #pragma unroll
    for (int r = 0; r < 4; r++)
        t[ty + 8 * r][tx] = W[(size_t)(k0 + ty + 8 * r) * N + n0 + tx];
    __syncthreads();
    #pragma unroll
    for (int r = 0; r < 4; r++) {
        size_t o = (size_t)(n0 + ty + 8 * r) * GK + k0 + tx;
        th[o] = __float2half_rn(t[tx][ty + 8 * r]);
    }
}

// ---------------- small fused kernels ----------------
struct MeanArgs { const float* x[2]; const float* mask[2]; float* out[2]; int S[2]; };
__global__ void mean_relu_kernel(MeanArgs a) {
    __shared__ float red[256];
    __shared__ float sinv;
    int z = blockIdx.z;
    int S = a.S[z];
    int b = blockIdx.y;
    const float* mp = a.mask[z] + (size_t)b * S;
    float s = 0.f;
    for (int t = threadIdx.x; t < S; t += 256) s += mp[t];
    red[threadIdx.x] = s;
    __syncthreads();
    for (int w = 128; w > 0; w >>= 1) {
        if (threadIdx.x < w) red[threadIdx.x] += red[threadIdx.x + w];
        __syncthreads();
    }
    if (threadIdx.x == 0) sinv = 1.f / red[0];
    __syncthreads();
    int d = blockIdx.x * 256 + threadIdx.x;
    const float* xp = a.x[z] + (size_t)b * S * D_ + d;
    float a0 = 0.f, a1 = 0.f, a2 = 0.f, a3 = 0.f;
    for (int t = 0; t < S; t += 4) {
        a0 = fmaf(xp[(size_t)(t + 0) * D_], mp[t + 0], a0);
        a1 = fmaf(xp[(size_t)(t + 1) * D_], mp[t + 1], a1);
        a2 = fmaf(xp[(size_t)(t + 2) * D_], mp[t + 2], a2);
        a3 = fmaf(xp[(size_t)(t + 3) * D_], mp[t + 3], a3);
    }
    a.out[z][b * D_ + d] = fmaxf(((a0 + a1) + (a2 + a3)) * sinv, 0.f);
}

// gate: k-parallel (4 k-groups x 128 n), smem reduce. grid (8, B, 2), block 512.
struct GateArgs { const float* mean[2]; const float* W[2]; const float* bias[2]; float* out[2]; };
__global__ __launch_bounds__(512) void gate_kernel(GateArgs a) {
    __shared__ float sm[D_];
    __shared__ float red[512];
    int z = blockIdx.z;
    int b = blockIdx.y;
    int tid = threadIdx.x;
    int g = tid >> 7;            // k-group 0..3
    int nl = tid & 127;
    const float* rmean = a.mean[z];
    const float* W = a.W[z];
    for (int k = tid; k < D_; k += 512) sm[k] = rmean[b * D_ + k];
    __syncthreads();
    int n = blockIdx.x * 128 + nl;
    int k0 = g * 256;
    float acc = 0.f;
    #pragma unroll 8
    for (int k = 0; k < 256; k++)
        acc = fmaf(sm[k0 + k], W[(size_t)(k0 + k) * D_ + n], acc);
    red[tid] = acc;
    __syncthreads();
    if (g == 0) {
        float t = red[nl] + red[nl + 128] + red[nl + 256] + red[nl + 384] + a.bias[z][n];
        a.out[z][b * D_ + n] = 1.f + 1.f / (1.f + __expf(-t));
    }
}

struct MemArgs { __half* K[2]; __half* V[2]; const float* mk[2]; const float* mv[2];
                 const float* gate[2]; int T[2]; };
__global__ void memtok_kernel(MemArgs a) {
    int z = blockIdx.y;
    int b = blockIdx.x;
    int i = threadIdx.x;
    int h = i >> 7;
    float kv = 32.f * a.mk[z][i];
    if (a.gate[z]) kv *= a.gate[z][b * D_ + i];
    size_t idx = ((size_t)(b * H_ + h) * a.T[z]) * DHD + (i & 127);
    a.K[z][idx] = __float2half_rn(kv);
    a.V[z][idx] = __float2half_rn(a.mv[z][i]);
}

// ---------------- mma.sync fp16 GEMM (3-stream merged, BK=64, 2-stage) ----------------
#define ROWB 72                              // 64 halves + pad (144B stride, conflict-free)
#define MAT_BYTES (128 * ROWB * 2)           // 18432
#define STAGE_BYTES (2 * MAT_BYTES)          // 36864
#define MMA_SMEM_BYTES (2 * STAGE_BYTES)     // 73728

struct GemmS {
    const __half *A, *B;
    const float *bias, *mask, *gate;
    __half *oK, *oQ, *oV;
    float* C;
    int S, T, hasMem;
};
struct Gemm3 { GemmS s[3]; int nby0, nby1; };

template <bool MASK, bool SPLIT>
__global__ __launch_bounds__(128, 2) void mma_gemm_kernel(Gemm3 ga, int N)
{
    extern __shared__ char smem[];
    uint32_t sbase = smem_u32(smem);
    int tid = threadIdx.x;
    int wid = tid >> 5, lane = tid & 31;
    int byg = blockIdx.y;
    int z, ybase;
    if (byg < ga.nby0) { z = 0; ybase = 0; }
    else if (byg < ga.nby0 + ga.nby1) { z = 1; ybase = ga.nby0; }
    else { z = 2; ybase = ga.nby0 + ga.nby1; }
    const GemmS s = ga.s[z];
    int bm = (byg - ybase) * 128, bn = blockIdx.x * 128;
    int wm = (wid & 1) * 64;
    int wn = (wid >> 1) * 64;

    const __half* srcs[2] = { s.A + (size_t)bm * GK, s.B + (size_t)bn * GK };

    float acc[4][8][4];
    #pragma unroll
    for (int i = 0; i < 4; i++)
        #pragma unroll
        for (int j = 0; j < 8; j++)
            #pragma unroll
            for (int k = 0; k < 4; k++) acc[i][j][k] = 0.f;

    int lrow = tid >> 3, lc = tid & 7;   // 16 rows x 8 chunks of 16B per pass
    auto load_stage = [&](int kc, int st2) {
        uint32_t st = sbase + st2 * STAGE_BYTES;
        int k0 = kc * 64;
        #pragma unroll
        for (int m = 0; m < 2; m++) {
            const __half* src = srcs[m];
            uint32_t dst = st + m * MAT_BYTES;
            #pragma unroll
            for (int it = 0; it < 8; it++) {
                int row = lrow + it * 16;
                cp16(dst + row * (ROWB * 2) + lc * 16, src + (size_t)row * GK + k0 + lc * 8);
            }
        }
        cp_commit();
    };

    load_stage(0, 0);

    const int NK = GK / 64;   // 16
    for (int kc = 0; kc < NK; kc++) {
        if (kc + 1 < NK) { load_stage(kc + 1, (kc + 1) & 1); cp_wait1(); }
        else cp_wait0();
        __syncthreads();
        uint32_t st = sbase + (kc & 1) * STAGE_BYTES;
        uint32_t sA = st, sB = st + MAT_BYTES;
        #pragma unroll
        for (int ks = 0; ks < 64; ks += 16) {
            uint32_t ah[4][4];
            int arow = wm + (lane & 15);
            int ak = ks + ((lane >> 4) << 3);
            #pragma unroll
            for (int mt = 0; mt < 4; mt++)
                ldmx4(ah[mt], sA + (uint32_t)(((arow + mt * 16) * ROWB + ak) * 2));
            int r = lane & 7, qsel = lane >> 3;
            #pragma unroll
            for (int nt = 0; nt < 4; nt++) {
                int nn = wn + nt * 16 + ((qsel >> 1) << 3) + r;
                int kk = ks + ((qsel & 1) << 3);
                uint32_t bh[4];
                ldmx4(bh, sB + (uint32_t)((nn * ROWB + kk) * 2));
                #pragma unroll
                for (int mt = 0; mt < 4; mt++) {
                    mma16816(acc[mt][nt * 2 + 0], ah[mt], bh[0], bh[1]);
                    mma16816(acc[mt][nt * 2 + 1], ah[mt], bh[2], bh[3]);
                }
            }
        }
        __syncthreads();
    }

    if (!SPLIT) {
        #pragma unroll
        for (int mt = 0; mt < 4; mt++) {
            int r0 = bm + wm + mt * 16 + (lane >> 2);
            float m0 = MASK ? s.mask[r0] : 1.f;
            float m1 = MASK ? s.mask[r0 + 8] : 1.f;
            #pragma unroll
            for (int nt = 0; nt < 8; nt++) {
                int col = bn + wn + nt * 8 + ((lane & 3) << 1);
                float2 bb = *(const float2*)&s.bias[col];
                float2 o0, o1;
                o0.x = (acc[mt][nt][0] + bb.x) * m0; o0.y = (acc[mt][nt][1] + bb.y) * m0;
                o1.x = (acc[mt][nt][2] + bb.x) * m1; o1.y = (acc[mt][nt][3] + bb.y) * m1;
                *(float2*)(s.C + (size_t)r0 * N + col) = o0;
                *(float2*)(s.C + (size_t)(r0 + 8) * N + col) = o1;
            }
        }
    } else {
        int colbase = bn + wn;
        int part = colbase >> 10;           // 0=k, 1=q, 2=v
        int hh = (colbase & 1023) >> 7;
        int dwarp = colbase & 127;
        int b = bm / s.S;
        int s0 = bm % s.S;
        size_t bh64 = (size_t)(b * H_ + hh);
        #pragma unroll
        for (int mt = 0; mt < 4; mt++) {
            int rl0 = wm + mt * 16 + (lane >> 2);
            int gr0 = bm + rl0;
            float mk0 = MASK ? s.mask[gr0] : 1.f;
            float mk1 = MASK ? s.mask[gr0 + 8] : 1.f;
            int s_0 = s0 + rl0, s_1 = s_0 + 8;
            #pragma unroll
            for (int nt = 0; nt < 8; nt++) {
                int d = dwarp + nt * 8 + ((lane & 3) << 1);
                int col = colbase + nt * 8 + ((lane & 3) << 1);
                float2 bb = *(const float2*)&s.bias[col];
                float x0 = (acc[mt][nt][0] + bb.x) * mk0;
                float y0 = (acc[mt][nt][1] + bb.y) * mk0;
                float x1 = (acc[mt][nt][2] + bb.x) * mk1;
                float y1 = (acc[mt][nt][3] + bb.y) * mk1;
                if (s.gate != nullptr && part < 2) {
                    float2 g2 = *(const float2*)&s.gate[b * D_ + hh * DHD + d];
                    x0 *= g2.x; y0 *= g2.y; x1 *= g2.x; y1 *= g2.y;
                }
                if (part == 0) {
                    store_h2(s.oK, (bh64 * s.T + (s_0 + s.hasMem)) * DHD + d, x0, y0);
                    store_h2(s.oK, (bh64 * s.T + (s_1 + s.hasMem)) * DHD + d, x1, y1);
                } else if (part == 1) {
                    store_h2(s.oQ, (bh64 * s.S + s_0) * DHD + d, x0, y0);
                    store_h2(s.oQ, (bh64 * s.S + s_1) * DHD + d, x1, y1);
                } else {
                    store_h2(s.oV, (bh64 * s.T + (s_0 + s.hasMem)) * DHD + d, x0, y0);
                    store_h2(s.oV, (bh64 * s.T + (s_1 + s.hasMem)) * DHD + d, x1, y1);
                }
            }
        }
    }
}

// ---------------- tensor-core flash attention (fp16, merged, f16x2 exp softmax) ----------------
#define APAD 136
constexpr int A_Q   = 0;
constexpr int A_ST0 = 128 * APAD * 2;
constexpr int A_STG = 2 * 64 * APAD * 2;
constexpr int A_K   = 0;
constexpr int A_V   = 64 * APAD * 2;
constexpr int A_KM  = A_ST0 + 2 * A_STG;
constexpr int ATT_SMEM_BYTES = A_KM + 2 * 64 * 4;

struct AttnS {
    const __half *K, *Q, *V;
    const float *mask, *resid;
    __half* outA;
    int S, T, hasMem;
};
struct Attn3 { AttnS s[3]; int nbx0, nbx1; };

__global__ __launch_bounds__(256, 2) void attn_mma_kernel(Attn3 aa)
{
    extern __shared__ char sm[];
    uint32_t sb = smem_u32(sm);
    float* km = (float*)(sm + A_KM);
    int tid = threadIdx.x, wid = tid >> 5, lane = tid & 31;
    int bxg = blockIdx.x;
    int z, xbase;
    if (bxg < aa.nbx0) { z = 0; xbase = 0; }
    else if (bxg < aa.nbx0 + aa.nbx1) { z = 1; xbase = aa.nbx0; }
    else { z = 2; xbase = aa.nbx0 + aa.nbx1; }
    const AttnS s = aa.s[z];
    int S = s.S, T = s.T, hasMem = s.hasMem;
    int b = blockIdx.z, h = blockIdx.y, m0 = (bxg - xbase) * 128;
    size_t bh = (size_t)(b * H_ + h);
    const __half* gQ = s.Q + (bh * S + m0) * DHD;
    const __half* gK = s.K + bh * T * DHD;
    const __half* gV = s.V + bh * T * DHD;

    const float SCL2  = 0.088388347648318447f * 1.4426950408889634f;
    const float NEGS2 = -1e9f * 0.088388347648318447f * 1.4426950408889634f;

    #pragma unroll
    for (int it = 0; it < 8; it++) {
        int id = tid + it * 256; int row = id >> 4, cc = id & 15;
        cp16(sb + A_Q + row * (APAD * 2) + cc * 16, gQ + row * DHD + cc * 8);
    }
    auto load_kv = [&](int kt, int st2) {
        int t0 = kt * 64;
        uint32_t st = sb + A_ST0 + st2 * A_STG;
        const __half* gm[2] = { gK, gV };
        #pragma unroll
        for (int m = 0; m < 2; m++) {
            #pragma unroll
            for (int it = 0; it < 4; it++) {
                int id = tid + it * 256; int row = id >> 4, cc = id & 15;
                int t = t0 + row;
                int tc = (t < T) ? t : (T - 1);
                int sz = (t < T) ? 16 : 0;
                cp16z(st + m * (64 * APAD * 2) + row * (APAD * 2) + cc * 16,
                      gm[m] + (size_t)tc * DHD + cc * 8, sz);
            }
        }
        if (tid < 64) {
            int t = t0 + tid;
            float bias = NEGS2;
            if (t < T) {
                if (hasMem && t == 0) bias = 0.f;
                else bias = (s.mask[(size_t)b * S + (t - hasMem)] != 0.f) ? 0.f : NEGS2;
            }
            km[st2 * 64 + tid] = bias;
        }
    };

    load_kv(0, 0);
    cp_commit();

    float o[16][4];
    #pragma unroll
    for (int i = 0; i < 16; i++) { o[i][0] = 0.f; o[i][1] = 0.f; o[i][2] = 0.f; o[i][3] = 0.f; }
    float mprev0 = -1e30f, mprev1 = -1e30f, lsum0 = 0.f, lsum1 = 0.f;
    int wm = wid * 16;
    int ntile = (T + 63) / 64;

    for (int kt = 0; kt < ntile; kt++) {
        if (kt + 1 < ntile) { load_kv(kt + 1, (kt + 1) & 1); cp_commit(); cp_wait1(); }
        else cp_wait0();
        __syncthreads();
        uint32_t st = sb + A_ST0 + (kt & 1) * A_STG;

        float sf[8][4];
        #pragma unroll
        for (int i = 0; i < 8; i++) { sf[i][0]=0.f; sf[i][1]=0.f; sf[i][2]=0.f; sf[i][3]=0.f; }
        #pragma unroll
        for (int ks = 0; ks < 128; ks += 16) {
            int arow = wm + (lane & 15), ak = ks + ((lane >> 4) << 3);
            uint32_t ah[4];
            ldmx4(ah, sb + A_Q + (uint32_t)(arow * APAD + ak) * 2);
            int r = lane & 7, qs = lane >> 3;
            #pragma unroll
            for (int pr = 0; pr < 4; pr++) {
                int nn = pr * 16 + ((qs >> 1) << 3) + r;
                int kk2 = ks + ((qs & 1) << 3);
                uint32_t bh4[4];
                ldmx4(bh4, st + A_K + (uint32_t)(nn * APAD + kk2) * 2);
                mma16816(sf[pr * 2 + 0], ah, bh4[0], bh4[1]);
                mma16816(sf[pr * 2 + 1], ah, bh4[2], bh4[3]);
            }
        }
        const float* kmc = km + (kt & 1) * 64;
        float mx0 = mprev0, mx1 = mprev1;
        #pragma unroll
        for (int nt = 0; nt < 8; nt++) {
            int c0 = nt * 8 + ((lane & 3) << 1);
            float kb0 = kmc[c0], kb1 = kmc[c0 + 1];
            sf[nt][0] = fmaf(sf[nt][0], SCL2, kb0);
            sf[nt][1] = fmaf(sf[nt][1], SCL2, kb1);
            sf[nt][2] = fmaf(sf[nt][2], SCL2, kb0);
            sf[nt][3] = fmaf(sf[nt][3], SCL2, kb1);
            mx0 = fmaxf(mx0, fmaxf(sf[nt][0], sf[nt][1]));
            mx1 = fmaxf(mx1, fmaxf(sf[nt][2], sf[nt][3]));
        }
        mx0 = fmaxf(mx0, __shfl_xor_sync(0xffffffffu, mx0, 1));
        mx0 = fmaxf(mx0, __shfl_xor_sync(0xffffffffu, mx0, 2));
        mx1 = fmaxf(mx1, __shfl_xor_sync(0xffffffffu, mx1, 1));
        mx1 = fmaxf(mx1, __shfl_xor_sync(0xffffffffu, mx1, 2));
        float corr0 = exp2f(mprev0 - mx0), corr1 = exp2f(mprev1 - mx1);
        mprev0 = mx0; mprev1 = mx1;
        // f16x2 exp: two exps per MUFU op; result IS the fp16 P fragment
        uint32_t p2[8][2];
        float ps0 = 0.f, ps1 = 0.f;
        #pragma unroll
        for (int nt = 0; nt < 8; nt++) {
            p2[nt][0] = h2exp2_u32(sf[nt][0] - mx0, sf[nt][1] - mx0);
            p2[nt][1] = h2exp2_u32(sf[nt][2] - mx1, sf[nt][3] - mx1);
            float2 f0 = __half22float2(*(__half2*)&p2[nt][0]);
            float2 f1 = __half22float2(*(__half2*)&p2[nt][1]);
            ps0 += f0.x + f0.y;
            ps1 += f1.x + f1.y;
        }
        ps0 += __shfl_xor_sync(0xffffffffu, ps0, 1);
        ps0 += __shfl_xor_sync(0xffffffffu, ps0, 2);
        ps1 += __shfl_xor_sync(0xffffffffu, ps1, 1);
        ps1 += __shfl_xor_sync(0xffffffffu, ps1, 2);
        lsum0 = lsum0 * corr0 + ps0;
        lsum1 = lsum1 * corr1 + ps1;
        if (kt > 0) {
            #pragma unroll
            for (int dd = 0; dd < 16; dd++) {
                o[dd][0] *= corr0; o[dd][1] *= corr0;
                o[dd][2] *= corr1; o[dd][3] *= corr1;
            }
        }
        int mi = lane >> 3, rr = lane & 7;
        #pragma unroll
        for (int kk = 0; kk < 4; kk++) {
            uint32_t ph4[4];
            ph4[0] = p2[2 * kk][0];
            ph4[1] = p2[2 * kk][1];
            ph4[2] = p2[2 * kk + 1][0];
            ph4[3] = p2[2 * kk + 1][1];
            #pragma unroll
            for (int db = 0; db < 8; db++) {
                uint32_t voff = (uint32_t)((kk * 16 + (mi & 1) * 8 + rr) * APAD
                                           + db * 16 + (mi >> 1) * 8) * 2;
                uint32_t vh4[4];
                ldmx4t(vh4, st + A_V + voff);
                mma16816(o[db * 2],     ph4, vh4[0], vh4[1]);
                mma16816(o[db * 2 + 1], ph4, vh4[2], vh4[3]);
            }
        }
        __syncthreads();
    }

    float i0 = 1.f / lsum0, i1 = 1.f / lsum1;
    int g = lane >> 2;
    size_t row0 = (size_t)(b * S + m0 + wm + g);
    const float* rs0 = s.resid + row0 * D_ + h * DHD;
    size_t ob0 = row0 * D_ + h * DHD;
    #pragma unroll
    for (int dd = 0; dd < 16; dd++) {
        int d = dd * 8 + ((lane & 3) << 1);
        float2 rv0 = *(const float2*)(rs0 + d);
        float2 rv1 = *(const float2*)(rs0 + 8 * D_ + d);
        store_h2(s.outA, ob0 + d,          rv0.x + o[dd][0] * i0, rv0.y + o[dd][1] * i0);
        store_h2(s.outA, ob0 + 8 * D_ + d, rv1.x + o[dd][2] * i1, rv1.y + o[dd][3] * i1);
    }
}

// ---------------- launch ----------------
extern "C" void kernel_launch(void* const* d_in, const int* in_sizes, int n_in,
                              void* d_out, int out_size) {
    const float* v      = (const float*)d_in[0];
    const float* q      = (const float*)d_in[1];
    const float* c      = (const float*)d_in[2];
    const float* v_mask = (const float*)d_in[3];
    const float* q_mask = (const float*)d_in[4];
    const float* c_mask = (const float*)d_in[5];
    const float* Wv4q   = (const float*)d_in[6];
    const float* bv4q   = (const float*)d_in[7];
    const float* Wq4v   = (const float*)d_in[8];
    const float* bq4v   = (const float*)d_in[9];
    const float* Wv     = (const float*)d_in[10];
    const float* bv     = (const float*)d_in[11];
    const float* Wq     = (const float*)d_in[12];
    const float* bq     = (const float*)d_in[13];
    const float* Wc     = (const float*)d_in[14];
    const float* bcin   = (const float*)d_in[15];
    const float* m_v_k  = (const float*)d_in[16];
    const float* m_v_v  = (const float*)d_in[17];
    const float* m_c_k  = (const float*)d_in[18];
    const float* m_c_v  = (const float*)d_in[19];
    const float* Wvo    = (const float*)d_in[20];
    const float* bvo    = (const float*)d_in[21];
    const float* Wqo    = (const float*)d_in[22];
    const float* bqo    = (const float*)d_in[23];
    const float* Wco    = (const float*)d_in[24];
    const float* bco    = (const float*)d_in[25];
    (void)in_sizes; (void)n_in; (void)out_size;

    float *gv4q, *gq4v, *mnv, *mnq;
    __half *a_v, *a_q, *a_c, *wt;
    __half *vK,*vQ,*vV, *qK,*qQ,*qV, *cK,*cQ,*cV;
    cudaGetSymbolAddress((void**)&gv4q,  g_gate_v4q);
    cudaGetSymbolAddress((void**)&gq4v,  g_gate_q4v);
    cudaGetSymbolAddress((void**)&mnv,   g_mean_v);
    cudaGetSymbolAddress((void**)&mnq,   g_mean_q);
    cudaGetSymbolAddress((void**)&a_v,   g_a_v);
    cudaGetSymbolAddress((void**)&a_q,   g_a_q);
    cudaGetSymbolAddress((void**)&a_c,   g_a_c);
    cudaGetSymbolAddress((void**)&wt,    g_wt);
    cudaGetSymbolAddress((void**)&vK, g_vK); cudaGetSymbolAddress((void**)&vQ, g_vQ);
    cudaGetSymbolAddress((void**)&vV, g_vV);
    cudaGetSymbolAddress((void**)&qK, g_qK); cudaGetSymbolAddress((void**)&qQ, g_qQ);
    cudaGetSymbolAddress((void**)&qV, g_qV);
    cudaGetSymbolAddress((void**)&cK, g_cK); cudaGetSymbolAddress((void**)&cQ, g_cQ);
    cudaGetSymbolAddress((void**)&cV, g_cV);

    cudaFuncSetAttribute(mma_gemm_kernel<true, true>,   cudaFuncAttributeMaxDynamicSharedMemorySize, MMA_SMEM_BYTES);
    cudaFuncSetAttribute(mma_gemm_kernel<false, false>, cudaFuncAttributeMaxDynamicSharedMemorySize, MMA_SMEM_BYTES);
    cudaFuncSetAttribute(attn_mma_kernel, cudaFuncAttributeMaxDynamicSharedMemorySize, ATT_SMEM_BYTES);

    static cudaStream_t s1 = nullptr, s2 = nullptr;
    static cudaEvent_t e0 = nullptr, e1 = nullptr, e2 = nullptr;
    if (s1 == nullptr) {
        cudaStreamCreateWithFlags(&s1, cudaStreamNonBlocking);
        cudaStreamCreateWithFlags(&s2, cudaStreamNonBlocking);
        cudaEventCreateWithFlags(&e0, cudaEventDisableTiming);
        cudaEventCreateWithFlags(&e1, cudaEventDisableTiming);
        cudaEventCreateWithFlags(&e2, cudaEventDisableTiming);
    }

    const size_t WO_V = 0, WO_Q = 3145728, WO_C = 6291456;
    const size_t WO_VO = 9437184, WO_QO = 10485760, WO_CO = 11534336;

    // fork prologue: s1 = wT, s2 = act, main = mean->gate->memtok
    cudaEventRecord(e0, 0);
    cudaStreamWaitEvent(s1, e0, 0);
    cudaStreamWaitEvent(s2, e0, 0);
    {
        WTArgs wa;
        wa.W[0] = Wv;  wa.out[0] = wt + WO_V;  wa.N[0] = N3;
        wa.W[1] = Wq;  wa.out[1] = wt + WO_Q;  wa.N[1] = N3;
        wa.W[2] = Wc;  wa.out[2] = wt + WO_C;  wa.N[2] = N3;
        wa.W[3] = Wvo; wa.out[3] = wt + WO_VO; wa.N[3] = D_;
        wa.W[4] = Wqo; wa.out[4] = wt + WO_QO; wa.N[4] = D_;
        wa.W[5] = Wco; wa.out[5] = wt + WO_CO; wa.N[5] = D_;
        cvt_wT_kernel<<<dim3(N3 / 32, 32, 6), dim3(32, 8), 0, s1>>>(wa);
    }
    {
        ActArgs aa;
        aa.x[0] = v; aa.out[0] = a_v; aa.nblk0 = 16384;
        aa.x[1] = q; aa.out[1] = a_q; aa.nblk1 = 8192;
        aa.x[2] = c; aa.out[2] = a_c;
        cvt_act_kernel<<<16384 + 8192 + 16384, 256, 0, s2>>>(aa);
    }
    {
        MeanArgs ma;
        ma.x[0] = v; ma.mask[0] = v_mask; ma.out[0] = mnv; ma.S[0] = SV;
        ma.x[1] = q; ma.mask[1] = q_mask; ma.out[1] = mnq; ma.S[1] = SQ;
        mean_relu_kernel<<<dim3(4, B_, 2), 256>>>(ma);
    }
    {
        GateArgs ga;
        ga.mean[0] = mnv; ga.W[0] = Wv4q; ga.bias[0] = bv4q; ga.out[0] = gv4q;
        ga.mean[1] = mnq; ga.W[1] = Wq4v; ga.bias[1] = bq4v; ga.out[1] = gq4v;
        gate_kernel<<<dim3(8, B_, 2), 512>>>(ga);
    }
    {
        MemArgs me;
        me.K[0] = vK; me.V[0] = vV; me.mk[0] = m_v_k; me.mv[0] = m_v_v;
        me.gate[0] = gq4v; me.T[0] = SV + 1;
        me.K[1] = cK; me.V[1] = cV; me.mk[1] = m_c_k; me.mv[1] = m_c_v;
        me.gate[1] = nullptr; me.T[1] = SC + 1;
        memtok_kernel<<<dim3(B_, 2), 1024>>>(me);
    }
    cudaEventRecord(e1, s1);
    cudaEventRecord(e2, s2);
    cudaStreamWaitEvent(0, e1, 0);
    cudaStreamWaitEvent(0, e2, 0);

    // QKV projections (merged 3 streams)
    {
        Gemm3 g3{};
        g3.s[0] = { a_v, wt + WO_V, bv,   v_mask, gq4v, vK, vQ, vV, nullptr, SV, SV + 1, 1 };
        g3.s[1] = { a_q, wt + WO_Q, bq,   q_mask, gv4q, qK, qQ, qV, nullptr, SQ, SQ,     0 };
        g3.s[2] = { a_c, wt + WO_C, bcin, c_mask, nullptr, cK, cQ, cV, nullptr, SC, SC + 1, 1 };
        g3.nby0 = 128; g3.nby1 = 64;
        mma_gemm_kernel<true, true><<<dim3(24, 320), 128, MMA_SMEM_BYTES>>>(g3, N3);
    }
    // attention (merged 3 streams)
    {
        Attn3 a3{};
        a3.s[0] = { vK, vQ, vV, v_mask, v, a_v, SV, SV + 1, 1 };
        a3.s[1] = { qK, qQ, qV, q_mask, q, a_q, SQ, SQ,     0 };
        a3.s[2] = { cK, cQ, cV, c_mask, c, a_c, SC, SC + 1, 1 };
        a3.nbx0 = SV / 128; a3.nbx1 = SQ / 128;
        attn_mma_kernel<<<dim3(SV / 128 + SQ / 128 + SC / 128, H_, B_), 256, ATT_SMEM_BYTES>>>(a3);
    }
    // output projections (merged 3 streams)
    {
        float* out = (float*)d_out;
        Gemm3 g3{};
        g3.s[0] = { a_v, wt + WO_VO, bvo, nullptr, nullptr, nullptr, nullptr, nullptr,
                    out, 0, 0, 0 };
        g3.s[1] = { a_q, wt + WO_QO, bqo, nullptr, nullptr, nullptr, nullptr, nullptr,
                    out + (size_t)B_ * SV * D_, 0, 0, 0 };
        g3.s[2] = { a_c, wt + WO_CO, bco, nullptr, nullptr, nullptr, nullptr, nullptr,
                    out + (size_t)B_ * (SV + SQ) * D_, 0, 0, 0 };
        g3.nby0 = 128; g3.nby1 = 64;
        mma_gemm_kernel<false, false><<<dim3(8, 320), 128, MMA_SMEM_BYTES>>>(g3, D_);
    }
}